// round 2
// baseline (speedup 1.0000x reference)
#include <cuda_runtime.h>

// Problem constants
#define BATCH 2
#define SEQL  2048
#define DMODEL 1024
#define NHEAD 16
#define DHEAD 64
#define BLROWS (BATCH * SEQL)   // 4096

// Scratch: qh, kh, vh, att  (each BLROWS x DMODEL fp32)
__device__ float g_scratch[(size_t)4 * BLROWS * DMODEL];

// ---------------------------------------------------------------------------
// 128x128x8 fp32 GEMM: C[M,N] = A[M,K] @ B[K,N]   (row-major, all dims %128==0)
// 256 threads, 8x8 per-thread micro tile.
// ---------------------------------------------------------------------------
__global__ __launch_bounds__(256) void sgemm128(const float* __restrict__ A,
                                                const float* __restrict__ B,
                                                float* __restrict__ C,
                                                int M, int N, int K) {
    __shared__ float As[8][128];   // [k][m]
    __shared__ float Bs[8][128];   // [k][n]

    const int bm = blockIdx.y;
    const int bn = blockIdx.x;
    const int tid = threadIdx.x;
    const int tx = tid & 15;       // 0..15 -> n
    const int ty = tid >> 4;       // 0..15 -> m

    const float* Ab = A + (size_t)bm * 128 * K;
    const float* Bb = B + (size_t)bn * 128;

    // load mapping
    const int la_m = tid >> 1;          // 0..127
    const int la_k = (tid & 1) * 4;     // 0 or 4
    const int lb_k = tid >> 5;          // 0..7
    const int lb_n = (tid & 31) * 4;    // 0..124

    float c[8][8];
#pragma unroll
    for (int i = 0; i < 8; i++)
#pragma unroll
        for (int j = 0; j < 8; j++) c[i][j] = 0.f;

    for (int k0 = 0; k0 < K; k0 += 8) {
        float4 av = *(const float4*)(Ab + (size_t)la_m * K + k0 + la_k);
        float4 bv = *(const float4*)(Bb + (size_t)(k0 + lb_k) * N + lb_n);
        __syncthreads();
        As[la_k + 0][la_m] = av.x;
        As[la_k + 1][la_m] = av.y;
        As[la_k + 2][la_m] = av.z;
        As[la_k + 3][la_m] = av.w;
        *(float4*)&Bs[lb_k][lb_n] = bv;
        __syncthreads();
#pragma unroll
        for (int kk = 0; kk < 8; kk++) {
            float a[8], b[8];
            *(float4*)(a)     = *(const float4*)&As[kk][ty * 8];
            *(float4*)(a + 4) = *(const float4*)&As[kk][ty * 8 + 4];
            *(float4*)(b)     = *(const float4*)&Bs[kk][tx * 8];
            *(float4*)(b + 4) = *(const float4*)&Bs[kk][tx * 8 + 4];
#pragma unroll
            for (int i = 0; i < 8; i++)
#pragma unroll
                for (int j = 0; j < 8; j++) c[i][j] += a[i] * b[j];
        }
    }

#pragma unroll
    for (int i = 0; i < 8; i++) {
        float* dst = C + (size_t)(bm * 128 + ty * 8 + i) * N + bn * 128 + tx * 8;
        float4 v0 = {c[i][0], c[i][1], c[i][2], c[i][3]};
        float4 v1 = {c[i][4], c[i][5], c[i][6], c[i][7]};
        *(float4*)(dst)     = v0;
        *(float4*)(dst + 4) = v1;
    }
}

// ---------------------------------------------------------------------------
// Causal flash attention, 64x64 tiles, online softmax.
// grid: (L/64, H, B), block: 256 threads (16x16, 4x4 micro tile).
// OUT gets att in (B,L,H*DHEAD) layout; scale = softmax(scores)/sqrt(DHEAD).
// ---------------------------------------------------------------------------
__global__ __launch_bounds__(256) void attn64(const float* __restrict__ QH,
                                              const float* __restrict__ KH,
                                              const float* __restrict__ VH,
                                              float* __restrict__ OUT) {
    __shared__ float Qs[64][64];   // [d][q]
    __shared__ float KVs[64][64];  // K phase: [d][k]; V phase: [k][d]
    __shared__ float Ps[64][64];   // [k][q]

    const int qb = blockIdx.x;
    const int h  = blockIdx.y;
    const int b  = blockIdx.z;
    const int tid = threadIdx.x;
    const int tx = tid & 15;       // key / dhead dimension group
    const int ty = tid >> 4;       // query dimension group

    // Load Q tile transposed: Qs[d][q]
    {
        const int q  = tid >> 2;
        const int d0 = (tid & 3) << 4;
        const float* src = QH + (size_t)(b * SEQL + qb * 64 + q) * DMODEL + h * DHEAD + d0;
#pragma unroll
        for (int i = 0; i < 16; i += 4) {
            float4 v = *(const float4*)(src + i);
            Qs[d0 + i + 0][q] = v.x;
            Qs[d0 + i + 1][q] = v.y;
            Qs[d0 + i + 2][q] = v.z;
            Qs[d0 + i + 3][q] = v.w;
        }
    }

    float o[4][4];
    float m[4], l[4];
#pragma unroll
    for (int i = 0; i < 4; i++) {
        m[i] = -1e30f; l[i] = 0.f;
#pragma unroll
        for (int j = 0; j < 4; j++) o[i][j] = 0.f;
    }

    for (int kb = 0; kb <= qb; kb++) {
        __syncthreads();  // prev PV reads done (and Q load visible on 1st iter)
        // Load K tile transposed: KVs[d][k]
        {
            const int kk = tid >> 2;
            const int d0 = (tid & 3) << 4;
            const float* src = KH + (size_t)(b * SEQL + kb * 64 + kk) * DMODEL + h * DHEAD + d0;
#pragma unroll
            for (int i = 0; i < 16; i += 4) {
                float4 v = *(const float4*)(src + i);
                KVs[d0 + i + 0][kk] = v.x;
                KVs[d0 + i + 1][kk] = v.y;
                KVs[d0 + i + 2][kk] = v.z;
                KVs[d0 + i + 3][kk] = v.w;
            }
        }
        __syncthreads();

        // S = Q @ K^T  (4x4 per thread)
        float s[4][4];
#pragma unroll
        for (int i = 0; i < 4; i++)
#pragma unroll
            for (int j = 0; j < 4; j++) s[i][j] = 0.f;
#pragma unroll 8
        for (int d = 0; d < 64; d++) {
            float4 qv = *(const float4*)&Qs[d][ty << 2];
            float4 kv = *(const float4*)&KVs[d][tx << 2];
            float qa[4] = {qv.x, qv.y, qv.z, qv.w};
            float ka[4] = {kv.x, kv.y, kv.z, kv.w};
#pragma unroll
            for (int i = 0; i < 4; i++)
#pragma unroll
                for (int j = 0; j < 4; j++) s[i][j] += qa[i] * ka[j];
        }

        // causal mask only on the diagonal tile
        if (kb == qb) {
#pragma unroll
            for (int i = 0; i < 4; i++) {
                const int qg = (ty << 2) + i;
#pragma unroll
                for (int j = 0; j < 4; j++) {
                    const int kg = (tx << 2) + j;
                    if (kg > qg) s[i][j] = -1e30f;
                }
            }
        }

        // online softmax: each query row is owned by one aligned 16-lane group
#pragma unroll
        for (int i = 0; i < 4; i++) {
            float tmax = fmaxf(fmaxf(s[i][0], s[i][1]), fmaxf(s[i][2], s[i][3]));
#pragma unroll
            for (int off = 8; off > 0; off >>= 1)
                tmax = fmaxf(tmax, __shfl_xor_sync(0xffffffffu, tmax, off));
            const float mn = fmaxf(m[i], tmax);
            const float sc = __expf(m[i] - mn);
            float rs = 0.f;
#pragma unroll
            for (int j = 0; j < 4; j++) { s[i][j] = __expf(s[i][j] - mn); rs += s[i][j]; }
#pragma unroll
            for (int off = 8; off > 0; off >>= 1)
                rs += __shfl_xor_sync(0xffffffffu, rs, off);
            l[i] = l[i] * sc + rs;
            m[i] = mn;
#pragma unroll
            for (int j = 0; j < 4; j++) o[i][j] *= sc;
        }

        // write P transposed: Ps[k][q]
#pragma unroll
        for (int i = 0; i < 4; i++)
#pragma unroll
            for (int j = 0; j < 4; j++)
                Ps[(tx << 2) + j][(ty << 2) + i] = s[i][j];
        __syncthreads();  // S-phase reads of KVs done -> safe to overwrite with V

        // Load V tile natural: KVs[k][d]
        {
            const int kk = tid >> 2;
            const int d0 = (tid & 3) << 4;
            const float* src = VH + (size_t)(b * SEQL + kb * 64 + kk) * DMODEL + h * DHEAD + d0;
#pragma unroll
            for (int i = 0; i < 16; i += 4)
                *(float4*)&KVs[kk][d0 + i] = *(const float4*)(src + i);
        }
        __syncthreads();

        // O += P^T-layout @ V
#pragma unroll 8
        for (int kk = 0; kk < 64; kk++) {
            float4 pv = *(const float4*)&Ps[kk][ty << 2];
            float4 vv = *(const float4*)&KVs[kk][tx << 2];
            float pa[4] = {pv.x, pv.y, pv.z, pv.w};
            float va[4] = {vv.x, vv.y, vv.z, vv.w};
#pragma unroll
            for (int i = 0; i < 4; i++)
#pragma unroll
                for (int j = 0; j < 4; j++) o[i][j] += pa[i] * va[j];
        }
    }

    // epilogue: (softmax / sqrt(DHEAD)) @ V  ->  o / l * 0.125
#pragma unroll
    for (int i = 0; i < 4; i++) {
        const float inv = 0.125f / l[i];
        const int row = b * SEQL + qb * 64 + (ty << 2) + i;
        float* dst = OUT + (size_t)row * DMODEL + h * DHEAD + (tx << 2);
        float4 v = {o[i][0] * inv, o[i][1] * inv, o[i][2] * inv, o[i][3] * inv};
        *(float4*)dst = v;
    }
}

// ---------------------------------------------------------------------------
// Launch
// ---------------------------------------------------------------------------
extern "C" void kernel_launch(void* const* d_in, const int* in_sizes, int n_in,
                              void* d_out, int out_size) {
    const float* q  = (const float*)d_in[0];
    const float* k  = (const float*)d_in[1];
    const float* v  = (const float*)d_in[2];
    // d_in[3] = causal mask (bool) -- structure known, unused
    const float* Wq = (const float*)d_in[4];
    const float* Wk = (const float*)d_in[5];
    const float* Wv = (const float*)d_in[6];
    const float* Wo = (const float*)d_in[7];
    float* out = (float*)d_out;

    void* sp = nullptr;
    cudaGetSymbolAddress(&sp, g_scratch);
    float* qh  = (float*)sp;
    float* kh  = qh + (size_t)BLROWS * DMODEL;
    float* vh  = kh + (size_t)BLROWS * DMODEL;
    float* att = vh + (size_t)BLROWS * DMODEL;

    dim3 gg(DMODEL / 128, BLROWS / 128);
    sgemm128<<<gg, 256>>>(q, Wq, qh, BLROWS, DMODEL, DMODEL);
    sgemm128<<<gg, 256>>>(k, Wk, kh, BLROWS, DMODEL, DMODEL);
    sgemm128<<<gg, 256>>>(v, Wv, vh, BLROWS, DMODEL, DMODEL);
    attn64<<<dim3(SEQL / 64, NHEAD, BATCH), 256>>>(qh, kh, vh, att);
    sgemm128<<<gg, 256>>>(att, Wo, out, BLROWS, DMODEL, DMODEL);
}

// round 4
// speedup vs baseline: 1.5853x; 1.5853x over previous
#include <cuda_runtime.h>
#include <cuda_bf16.h>
#include <cstdint>

// Problem constants
#define BATCH 2
#define SEQL  2048
#define DMODEL 1024
#define NHEAD 16
#define DHEAD 64
#define BLROWS (BATCH * SEQL)   // 4096
#define GK 1024

// ---------------------------------------------------------------------------
// Scratch
// ---------------------------------------------------------------------------
__device__ float g_f32[(size_t)4 * BLROWS * DMODEL];              // qh,kh,vh,att
__device__ __nv_bfloat16 g_inhi[(size_t)BLROWS * DMODEL];
__device__ __nv_bfloat16 g_inlo[(size_t)BLROWS * DMODEL];
__device__ __nv_bfloat16 g_wthi[(size_t)DMODEL * DMODEL];
__device__ __nv_bfloat16 g_wtlo[(size_t)DMODEL * DMODEL];

// ---------------------------------------------------------------------------
// PTX helpers (sm_80-level: portable to compute_103 PTX target)
// ---------------------------------------------------------------------------
__device__ __forceinline__ uint32_t s2u(const void* p) {
    uint32_t a;
    asm("{ .reg .u64 t; cvta.to.shared.u64 t, %1; cvt.u32.u64 %0, t; }"
        : "=r"(a) : "l"(p));
    return a;
}

__device__ __forceinline__ void ldsm_x4(uint32_t* r, uint32_t addr) {
    asm volatile("ldmatrix.sync.aligned.m8n8.x4.shared.b16 {%0,%1,%2,%3}, [%4];"
                 : "=r"(r[0]), "=r"(r[1]), "=r"(r[2]), "=r"(r[3]) : "r"(addr));
}
__device__ __forceinline__ void ldsm_x2(uint32_t* r, uint32_t addr) {
    asm volatile("ldmatrix.sync.aligned.m8n8.x2.shared.b16 {%0,%1}, [%2];"
                 : "=r"(r[0]), "=r"(r[1]) : "r"(addr));
}
__device__ __forceinline__ void mma16816(float* d, const uint32_t* a, const uint32_t* b) {
    asm volatile("mma.sync.aligned.m16n8k16.row.col.f32.bf16.bf16.f32 "
                 "{%0,%1,%2,%3}, {%4,%5,%6,%7}, {%8,%9}, {%0,%1,%2,%3};"
                 : "+f"(d[0]), "+f"(d[1]), "+f"(d[2]), "+f"(d[3])
                 : "r"(a[0]), "r"(a[1]), "r"(a[2]), "r"(a[3]), "r"(b[0]), "r"(b[1]));
}
__device__ __forceinline__ void cpa16(uint32_t saddr, const void* g) {
    asm volatile("cp.async.cg.shared.global [%0], [%1], 16;" :: "r"(saddr), "l"(g));
}
#define CP_COMMIT() asm volatile("cp.async.commit_group;" ::: "memory")
#define CP_WAIT1()  asm volatile("cp.async.wait_group 1;" ::: "memory")
#define CP_WAIT0()  asm volatile("cp.async.wait_group 0;" ::: "memory")

// ---------------------------------------------------------------------------
// Conversion kernels: fp32 -> (bf16 hi, bf16 lo) split
// ---------------------------------------------------------------------------
__global__ __launch_bounds__(256) void split_bf16(const float* __restrict__ in,
                                                  __nv_bfloat16* __restrict__ hi,
                                                  __nv_bfloat16* __restrict__ lo,
                                                  int n4) {
    int i = blockIdx.x * blockDim.x + threadIdx.x;
    if (i >= n4) return;
    float4 v = ((const float4*)in)[i];
    __nv_bfloat16 h0 = __float2bfloat16(v.x);
    __nv_bfloat16 h1 = __float2bfloat16(v.y);
    __nv_bfloat16 h2 = __float2bfloat16(v.z);
    __nv_bfloat16 h3 = __float2bfloat16(v.w);
    __nv_bfloat16 l0 = __float2bfloat16(v.x - __bfloat162float(h0));
    __nv_bfloat16 l1 = __float2bfloat16(v.y - __bfloat162float(h1));
    __nv_bfloat16 l2 = __float2bfloat16(v.z - __bfloat162float(h2));
    __nv_bfloat16 l3 = __float2bfloat16(v.w - __bfloat162float(h3));
    ((__nv_bfloat162*)hi)[2 * i]     = __nv_bfloat162(h0, h1);
    ((__nv_bfloat162*)hi)[2 * i + 1] = __nv_bfloat162(h2, h3);
    ((__nv_bfloat162*)lo)[2 * i]     = __nv_bfloat162(l0, l1);
    ((__nv_bfloat162*)lo)[2 * i + 1] = __nv_bfloat162(l2, l3);
}

// W [K][N] fp32 -> Wt_hi/lo [N][K] bf16 (transposed split)
__global__ __launch_bounds__(256) void splitT_bf16(const float* __restrict__ W,
                                                   __nv_bfloat16* __restrict__ th,
                                                   __nv_bfloat16* __restrict__ tl) {
    __shared__ float t[32][33];
    const int tx = threadIdx.x, ty = threadIdx.y;
    const int n0 = blockIdx.x * 32, k0 = blockIdx.y * 32;
#pragma unroll
    for (int i = 0; i < 32; i += 8)
        t[ty + i][tx] = W[(size_t)(k0 + ty + i) * DMODEL + n0 + tx];
    __syncthreads();
#pragma unroll
    for (int i = 0; i < 32; i += 8) {
        float x = t[tx][ty + i];
        __nv_bfloat16 h = __float2bfloat16(x);
        __nv_bfloat16 l = __float2bfloat16(x - __bfloat162float(h));
        size_t o = (size_t)(n0 + ty + i) * DMODEL + k0 + tx;
        th[o] = h;
        tl[o] = l;
    }
}

// ---------------------------------------------------------------------------
// bf16 split-MMA GEMM: C[M,N] = A[M,K] @ W[K,N]
//   Ahi/Alo : [M][K] bf16, Bhi/Blo : [N][K] bf16 (pre-transposed weights)
// Block: 128x128, K-chunk 64, double-buffered cp.async, 256 thr (8 warps 64x32)
// grid (N/128, M/128)
// ---------------------------------------------------------------------------
#define BUF_B   16384u               // one 128x64 bf16 tile
#define STAGE_B 65536u               // 4 tiles (Ah, Al, Bh, Bl)
#define SMEM_GEMM (2u * STAGE_B)     // 131072

// load one pipeline stage (Ah,Al,Bh,Bl tiles for K-chunk k0) into stage s
__device__ __forceinline__ void stage_load(const __nv_bfloat16* __restrict__ Ahi,
                                           const __nv_bfloat16* __restrict__ Alo,
                                           const __nv_bfloat16* __restrict__ Bhi,
                                           const __nv_bfloat16* __restrict__ Blo,
                                           int am0, int bn0, int k0,
                                           uint32_t sbase, int tid) {
#pragma unroll
    for (int b = 0; b < 4; b++) {
        const __nv_bfloat16* g = (b == 0) ? Ahi : (b == 1) ? Alo : (b == 2) ? Bhi : Blo;
        const int r0 = (b < 2) ? am0 : bn0;
        const uint32_t sbuf = sbase + b * BUF_B;
#pragma unroll
        for (int t = 0; t < 4; t++) {
            int u = tid + t * 256;
            int row = u >> 3, c = u & 7;
            int sw = c ^ (row & 7);
            cpa16(sbuf + row * 128 + sw * 16,
                  g + (size_t)(r0 + row) * GK + k0 + c * 8);
        }
    }
}

__global__ __launch_bounds__(256) void gemm_mma(const __nv_bfloat16* __restrict__ Ahi,
                                                const __nv_bfloat16* __restrict__ Alo,
                                                const __nv_bfloat16* __restrict__ Bhi,
                                                const __nv_bfloat16* __restrict__ Blo,
                                                float* __restrict__ C, int N) {
    extern __shared__ char sm[];
    const uint32_t sb = s2u(sm);
    const int tid = threadIdx.x;
    const int wid = tid >> 5, lane = tid & 31;
    const int wm = wid & 1;          // 0..1 -> 64-row slab
    const int wn = wid >> 1;         // 0..3 -> 32-col slab
    const int bm = blockIdx.y, bn = blockIdx.x;
    const int am0 = bm * 128, bn0 = bn * 128;

    float acc[4][4][4];
#pragma unroll
    for (int i = 0; i < 4; i++)
#pragma unroll
        for (int j = 0; j < 4; j++)
#pragma unroll
            for (int r = 0; r < 4; r++) acc[i][j][r] = 0.f;

    stage_load(Ahi, Alo, Bhi, Blo, am0, bn0, 0, sb, tid);
    CP_COMMIT();

    const int NC = GK / 64;          // 16 chunks
    for (int c = 0; c < NC; c++) {
        if (c + 1 < NC) {
            stage_load(Ahi, Alo, Bhi, Blo, am0, bn0, (c + 1) * 64,
                       sb + ((c + 1) & 1) * STAGE_B, tid);
            CP_COMMIT();
            CP_WAIT1();
        } else {
            CP_WAIT0();
        }
        __syncthreads();

        const uint32_t base = sb + (c & 1) * STAGE_B;
        const int ra = lane & 15, ca = lane >> 4;
        const int rb = lane & 7,  cb = (lane >> 3) & 1;
#pragma unroll
        for (int ks = 0; ks < 4; ks++) {
            uint32_t ah[4][4], al[4][4];
#pragma unroll
            for (int i = 0; i < 4; i++) {
                int row = wm * 64 + i * 16 + ra;
                int ch = (ks * 2 + ca) ^ (row & 7);
                uint32_t ad = base + row * 128 + ch * 16;
                ldsm_x4(ah[i], ad);
                ldsm_x4(al[i], ad + BUF_B);
            }
            uint32_t bh[4][2], bl[4][2];
#pragma unroll
            for (int j = 0; j < 4; j++) {
                int row = wn * 32 + j * 8 + rb;
                int ch = (ks * 2 + cb) ^ (row & 7);
                uint32_t bd = base + 2 * BUF_B + row * 128 + ch * 16;
                ldsm_x2(bh[j], bd);
                ldsm_x2(bl[j], bd + BUF_B);
            }
#pragma unroll
            for (int i = 0; i < 4; i++)
#pragma unroll
                for (int j = 0; j < 4; j++) {
                    mma16816(acc[i][j], ah[i], bh[j]);
                    mma16816(acc[i][j], ah[i], bl[j]);
                    mma16816(acc[i][j], al[i], bh[j]);
                }
        }
        __syncthreads();
    }

    // epilogue: mma c-fragment layout -> global fp32
    const int r0 = lane >> 2, c0 = (lane & 3) * 2;
#pragma unroll
    for (int i = 0; i < 4; i++) {
#pragma unroll
        for (int j = 0; j < 4; j++) {
            const int grow = am0 + wm * 64 + i * 16 + r0;
            const int gcol = bn0 + wn * 32 + j * 8 + c0;
            float2 v0 = {acc[i][j][0], acc[i][j][1]};
            float2 v1 = {acc[i][j][2], acc[i][j][3]};
            *(float2*)(C + (size_t)grow * N + gcol)       = v0;
            *(float2*)(C + (size_t)(grow + 8) * N + gcol) = v1;
        }
    }
}

// ---------------------------------------------------------------------------
// Causal flash attention, 64x64 tiles, online softmax (unchanged, verified).
// ---------------------------------------------------------------------------
__global__ __launch_bounds__(256) void attn64(const float* __restrict__ QH,
                                              const float* __restrict__ KH,
                                              const float* __restrict__ VH,
                                              float* __restrict__ OUT) {
    __shared__ float Qs[64][64];
    __shared__ float KVs[64][64];
    __shared__ float Ps[64][64];

    const int qb = blockIdx.x;
    const int h  = blockIdx.y;
    const int b  = blockIdx.z;
    const int tid = threadIdx.x;
    const int tx = tid & 15;
    const int ty = tid >> 4;

    {
        const int q  = tid >> 2;
        const int d0 = (tid & 3) << 4;
        const float* src = QH + (size_t)(b * SEQL + qb * 64 + q) * DMODEL + h * DHEAD + d0;
#pragma unroll
        for (int i = 0; i < 16; i += 4) {
            float4 v = *(const float4*)(src + i);
            Qs[d0 + i + 0][q] = v.x;
            Qs[d0 + i + 1][q] = v.y;
            Qs[d0 + i + 2][q] = v.z;
            Qs[d0 + i + 3][q] = v.w;
        }
    }

    float o[4][4];
    float m[4], l[4];
#pragma unroll
    for (int i = 0; i < 4; i++) {
        m[i] = -1e30f; l[i] = 0.f;
#pragma unroll
        for (int j = 0; j < 4; j++) o[i][j] = 0.f;
    }

    for (int kb = 0; kb <= qb; kb++) {
        __syncthreads();
        {
            const int kk = tid >> 2;
            const int d0 = (tid & 3) << 4;
            const float* src = KH + (size_t)(b * SEQL + kb * 64 + kk) * DMODEL + h * DHEAD + d0;
#pragma unroll
            for (int i = 0; i < 16; i += 4) {
                float4 v = *(const float4*)(src + i);
                KVs[d0 + i + 0][kk] = v.x;
                KVs[d0 + i + 1][kk] = v.y;
                KVs[d0 + i + 2][kk] = v.z;
                KVs[d0 + i + 3][kk] = v.w;
            }
        }
        __syncthreads();

        float s[4][4];
#pragma unroll
        for (int i = 0; i < 4; i++)
#pragma unroll
            for (int j = 0; j < 4; j++) s[i][j] = 0.f;
#pragma unroll 8
        for (int d = 0; d < 64; d++) {
            float4 qv = *(const float4*)&Qs[d][ty << 2];
            float4 kv = *(const float4*)&KVs[d][tx << 2];
            float qa[4] = {qv.x, qv.y, qv.z, qv.w};
            float ka[4] = {kv.x, kv.y, kv.z, kv.w};
#pragma unroll
            for (int i = 0; i < 4; i++)
#pragma unroll
                for (int j = 0; j < 4; j++) s[i][j] += qa[i] * ka[j];
        }

        if (kb == qb) {
#pragma unroll
            for (int i = 0; i < 4; i++) {
                const int qg = (ty << 2) + i;
#pragma unroll
                for (int j = 0; j < 4; j++) {
                    const int kg = (tx << 2) + j;
                    if (kg > qg) s[i][j] = -1e30f;
                }
            }
        }

#pragma unroll
        for (int i = 0; i < 4; i++) {
            float tmax = fmaxf(fmaxf(s[i][0], s[i][1]), fmaxf(s[i][2], s[i][3]));
#pragma unroll
            for (int off = 8; off > 0; off >>= 1)
                tmax = fmaxf(tmax, __shfl_xor_sync(0xffffffffu, tmax, off));
            const float mn = fmaxf(m[i], tmax);
            const float sc = __expf(m[i] - mn);
            float rs = 0.f;
#pragma unroll
            for (int j = 0; j < 4; j++) { s[i][j] = __expf(s[i][j] - mn); rs += s[i][j]; }
#pragma unroll
            for (int off = 8; off > 0; off >>= 1)
                rs += __shfl_xor_sync(0xffffffffu, rs, off);
            l[i] = l[i] * sc + rs;
            m[i] = mn;
#pragma unroll
            for (int j = 0; j < 4; j++) o[i][j] *= sc;
        }

#pragma unroll
        for (int i = 0; i < 4; i++)
#pragma unroll
            for (int j = 0; j < 4; j++)
                Ps[(tx << 2) + j][(ty << 2) + i] = s[i][j];
        __syncthreads();

        {
            const int kk = tid >> 2;
            const int d0 = (tid & 3) << 4;
            const float* src = VH + (size_t)(b * SEQL + kb * 64 + kk) * DMODEL + h * DHEAD + d0;
#pragma unroll
            for (int i = 0; i < 16; i += 4)
                *(float4*)&KVs[kk][d0 + i] = *(const float4*)(src + i);
        }
        __syncthreads();

#pragma unroll 8
        for (int kk = 0; kk < 64; kk++) {
            float4 pv = *(const float4*)&Ps[kk][ty << 2];
            float4 vv = *(const float4*)&KVs[kk][tx << 2];
            float pa[4] = {pv.x, pv.y, pv.z, pv.w};
            float va[4] = {vv.x, vv.y, vv.z, vv.w};
#pragma unroll
            for (int i = 0; i < 4; i++)
#pragma unroll
                for (int j = 0; j < 4; j++) o[i][j] += pa[i] * va[j];
        }
    }

#pragma unroll
    for (int i = 0; i < 4; i++) {
        const float inv = 0.125f / l[i];
        const int row = b * SEQL + qb * 64 + (ty << 2) + i;
        float* dst = OUT + (size_t)row * DMODEL + h * DHEAD + (tx << 2);
        float4 v = {o[i][0] * inv, o[i][1] * inv, o[i][2] * inv, o[i][3] * inv};
        *(float4*)dst = v;
    }
}

// ---------------------------------------------------------------------------
// Launch
// ---------------------------------------------------------------------------
extern "C" void kernel_launch(void* const* d_in, const int* in_sizes, int n_in,
                              void* d_out, int out_size) {
    const float* q  = (const float*)d_in[0];
    const float* k  = (const float*)d_in[1];
    const float* v  = (const float*)d_in[2];
    const float* Wq = (const float*)d_in[4];
    const float* Wk = (const float*)d_in[5];
    const float* Wv = (const float*)d_in[6];
    const float* Wo = (const float*)d_in[7];
    float* out = (float*)d_out;

    void *pf32, *pih, *pil, *pwh, *pwl;
    cudaGetSymbolAddress(&pf32, g_f32);
    cudaGetSymbolAddress(&pih, g_inhi);
    cudaGetSymbolAddress(&pil, g_inlo);
    cudaGetSymbolAddress(&pwh, g_wthi);
    cudaGetSymbolAddress(&pwl, g_wtlo);
    float* qh  = (float*)pf32;
    float* kh  = qh + (size_t)BLROWS * DMODEL;
    float* vh  = kh + (size_t)BLROWS * DMODEL;
    float* att = vh + (size_t)BLROWS * DMODEL;
    __nv_bfloat16* inhi = (__nv_bfloat16*)pih;
    __nv_bfloat16* inlo = (__nv_bfloat16*)pil;
    __nv_bfloat16* wthi = (__nv_bfloat16*)pwh;
    __nv_bfloat16* wtlo = (__nv_bfloat16*)pwl;

    cudaFuncSetAttribute(gemm_mma, cudaFuncAttributeMaxDynamicSharedMemorySize, SMEM_GEMM);

    const int n4 = (BLROWS * DMODEL) / 4;
    const dim3 cg((n4 + 255) / 256);
    const dim3 tg(DMODEL / 32, DMODEL / 32), tb(32, 8);
    const dim3 gg(DMODEL / 128, BLROWS / 128);

    const float* ins[3] = {q, k, v};
    const float* ws[3]  = {Wq, Wk, Wv};
    float* outs[3]      = {qh, kh, vh};
    for (int i = 0; i < 3; i++) {
        split_bf16<<<cg, 256>>>(ins[i], inhi, inlo, n4);
        splitT_bf16<<<tg, tb>>>(ws[i], wthi, wtlo);
        gemm_mma<<<gg, 256, SMEM_GEMM>>>(inhi, inlo, wthi, wtlo, outs[i], DMODEL);
    }

    attn64<<<dim3(SEQL / 64, NHEAD, BATCH), 256>>>(qh, kh, vh, att);

    split_bf16<<<cg, 256>>>(att, inhi, inlo, n4);
    splitT_bf16<<<tg, tb>>>(Wo, wthi, wtlo);
    gemm_mma<<<gg, 256, SMEM_GEMM>>>(inhi, inlo, wthi, wtlo, out, DMODEL);
}

// round 5
// speedup vs baseline: 3.4147x; 2.1539x over previous
#include <cuda_runtime.h>
#include <cuda_bf16.h>
#include <cstdint>

// Problem constants
#define BATCH 2
#define SEQL  2048
#define DMODEL 1024
#define NHEAD 16
#define DHEAD 64
#define BLROWS (BATCH * SEQL)   // 4096
#define GK 1024

// ---------------------------------------------------------------------------
// Scratch
// ---------------------------------------------------------------------------
__device__ float g_f32[(size_t)4 * BLROWS * DMODEL];              // qh,kh,vh,att
__device__ __nv_bfloat16 g_inhi[(size_t)BLROWS * DMODEL];
__device__ __nv_bfloat16 g_inlo[(size_t)BLROWS * DMODEL];
__device__ __nv_bfloat16 g_wthi[(size_t)DMODEL * DMODEL];
__device__ __nv_bfloat16 g_wtlo[(size_t)DMODEL * DMODEL];
__device__ __nv_bfloat16 g_qhi[(size_t)BLROWS * DMODEL];
__device__ __nv_bfloat16 g_qlo[(size_t)BLROWS * DMODEL];
__device__ __nv_bfloat16 g_khi[(size_t)BLROWS * DMODEL];
__device__ __nv_bfloat16 g_klo[(size_t)BLROWS * DMODEL];
__device__ __nv_bfloat16 g_vthi[(size_t)BLROWS * DMODEL];   // [b,h,d,key]
__device__ __nv_bfloat16 g_vtlo[(size_t)BLROWS * DMODEL];

// ---------------------------------------------------------------------------
// PTX helpers (sm_80-level, portable to compute_103 PTX target)
// ---------------------------------------------------------------------------
__device__ __forceinline__ uint32_t s2u(const void* p) {
    uint32_t a;
    asm("{ .reg .u64 t; cvta.to.shared.u64 t, %1; cvt.u32.u64 %0, t; }"
        : "=r"(a) : "l"(p));
    return a;
}
__device__ __forceinline__ void ldsm_x4(uint32_t* r, uint32_t addr) {
    asm volatile("ldmatrix.sync.aligned.m8n8.x4.shared.b16 {%0,%1,%2,%3}, [%4];"
                 : "=r"(r[0]), "=r"(r[1]), "=r"(r[2]), "=r"(r[3]) : "r"(addr));
}
__device__ __forceinline__ void ldsm_x2(uint32_t* r, uint32_t addr) {
    asm volatile("ldmatrix.sync.aligned.m8n8.x2.shared.b16 {%0,%1}, [%2];"
                 : "=r"(r[0]), "=r"(r[1]) : "r"(addr));
}
__device__ __forceinline__ void mma16816(float* d, const uint32_t* a, const uint32_t* b) {
    asm volatile("mma.sync.aligned.m16n8k16.row.col.f32.bf16.bf16.f32 "
                 "{%0,%1,%2,%3}, {%4,%5,%6,%7}, {%8,%9}, {%0,%1,%2,%3};"
                 : "+f"(d[0]), "+f"(d[1]), "+f"(d[2]), "+f"(d[3])
                 : "r"(a[0]), "r"(a[1]), "r"(a[2]), "r"(a[3]), "r"(b[0]), "r"(b[1]));
}
__device__ __forceinline__ void cpa16(uint32_t saddr, const void* g) {
    asm volatile("cp.async.cg.shared.global [%0], [%1], 16;" :: "r"(saddr), "l"(g));
}
#define CP_COMMIT() asm volatile("cp.async.commit_group;" ::: "memory")
#define CP_WAIT1()  asm volatile("cp.async.wait_group 1;" ::: "memory")
#define CP_WAIT0()  asm volatile("cp.async.wait_group 0;" ::: "memory")

__device__ __forceinline__ uint32_t packbf(float lo, float hi) {
    uint32_t d;
    asm("cvt.rn.bf16x2.f32 %0, %1, %2;" : "=r"(d) : "f"(hi), "f"(lo));
    return d;
}

// ---------------------------------------------------------------------------
// Conversion kernels
// ---------------------------------------------------------------------------
__global__ __launch_bounds__(256) void split_bf16(const float* __restrict__ in,
                                                  __nv_bfloat16* __restrict__ hi,
                                                  __nv_bfloat16* __restrict__ lo,
                                                  int n4) {
    int i = blockIdx.x * blockDim.x + threadIdx.x;
    if (i >= n4) return;
    float4 v = ((const float4*)in)[i];
    __nv_bfloat16 h0 = __float2bfloat16(v.x);
    __nv_bfloat16 h1 = __float2bfloat16(v.y);
    __nv_bfloat16 h2 = __float2bfloat16(v.z);
    __nv_bfloat16 h3 = __float2bfloat16(v.w);
    __nv_bfloat16 l0 = __float2bfloat16(v.x - __bfloat162float(h0));
    __nv_bfloat16 l1 = __float2bfloat16(v.y - __bfloat162float(h1));
    __nv_bfloat16 l2 = __float2bfloat16(v.z - __bfloat162float(h2));
    __nv_bfloat16 l3 = __float2bfloat16(v.w - __bfloat162float(h3));
    ((__nv_bfloat162*)hi)[2 * i]     = __nv_bfloat162(h0, h1);
    ((__nv_bfloat162*)hi)[2 * i + 1] = __nv_bfloat162(h2, h3);
    ((__nv_bfloat162*)lo)[2 * i]     = __nv_bfloat162(l0, l1);
    ((__nv_bfloat162*)lo)[2 * i + 1] = __nv_bfloat162(l2, l3);
}

// W [K][N] fp32 -> Wt_hi/lo [N][K] bf16 (transposed split)
__global__ __launch_bounds__(256) void splitT_bf16(const float* __restrict__ W,
                                                   __nv_bfloat16* __restrict__ th,
                                                   __nv_bfloat16* __restrict__ tl) {
    __shared__ float t[32][33];
    const int tx = threadIdx.x, ty = threadIdx.y;
    const int n0 = blockIdx.x * 32, k0 = blockIdx.y * 32;
#pragma unroll
    for (int i = 0; i < 32; i += 8)
        t[ty + i][tx] = W[(size_t)(k0 + ty + i) * DMODEL + n0 + tx];
    __syncthreads();
#pragma unroll
    for (int i = 0; i < 32; i += 8) {
        float x = t[tx][ty + i];
        __nv_bfloat16 h = __float2bfloat16(x);
        __nv_bfloat16 l = __float2bfloat16(x - __bfloat162float(h));
        size_t o = (size_t)(n0 + ty + i) * DMODEL + k0 + tx;
        th[o] = h;
        tl[o] = l;
    }
}

// vh fp32 [b][tok][dmodel] -> Vt hi/lo [b,h,d][key]  (per-head transpose split)
// grid (SEQL/32, DHEAD/32, BATCH*NHEAD), block (32,8)
__global__ __launch_bounds__(256) void vsplitT(const float* __restrict__ V,
                                               __nv_bfloat16* __restrict__ th,
                                               __nv_bfloat16* __restrict__ tl) {
    __shared__ float t[32][33];
    const int tx = threadIdx.x, ty = threadIdx.y;
    const int t0 = blockIdx.x * 32, d0 = blockIdx.y * 32;
    const int bh = blockIdx.z;
    const int b = bh >> 4, h = bh & 15;
#pragma unroll
    for (int i = 0; i < 32; i += 8)
        t[ty + i][tx] = V[(size_t)(b * SEQL + t0 + ty + i) * DMODEL + h * DHEAD + d0 + tx];
    __syncthreads();
#pragma unroll
    for (int i = 0; i < 32; i += 8) {
        float x = t[tx][ty + i];
        __nv_bfloat16 hh = __float2bfloat16(x);
        __nv_bfloat16 ll = __float2bfloat16(x - __bfloat162float(hh));
        size_t o = (size_t)(bh * DHEAD + d0 + ty + i) * SEQL + t0 + tx;
        th[o] = hh;
        tl[o] = ll;
    }
}

// ---------------------------------------------------------------------------
// bf16 split-MMA GEMM (unchanged, verified R3)
// ---------------------------------------------------------------------------
#define BUF_B   16384u
#define STAGE_B 65536u
#define SMEM_GEMM (2u * STAGE_B)

__device__ __forceinline__ void stage_load(const __nv_bfloat16* __restrict__ Ahi,
                                           const __nv_bfloat16* __restrict__ Alo,
                                           const __nv_bfloat16* __restrict__ Bhi,
                                           const __nv_bfloat16* __restrict__ Blo,
                                           int am0, int bn0, int k0,
                                           uint32_t sbase, int tid) {
#pragma unroll
    for (int b = 0; b < 4; b++) {
        const __nv_bfloat16* g = (b == 0) ? Ahi : (b == 1) ? Alo : (b == 2) ? Bhi : Blo;
        const int r0 = (b < 2) ? am0 : bn0;
        const uint32_t sbuf = sbase + b * BUF_B;
#pragma unroll
        for (int t = 0; t < 4; t++) {
            int u = tid + t * 256;
            int row = u >> 3, c = u & 7;
            int sw = c ^ (row & 7);
            cpa16(sbuf + row * 128 + sw * 16,
                  g + (size_t)(r0 + row) * GK + k0 + c * 8);
        }
    }
}

__global__ __launch_bounds__(256) void gemm_mma(const __nv_bfloat16* __restrict__ Ahi,
                                                const __nv_bfloat16* __restrict__ Alo,
                                                const __nv_bfloat16* __restrict__ Bhi,
                                                const __nv_bfloat16* __restrict__ Blo,
                                                float* __restrict__ C, int N) {
    extern __shared__ char sm[];
    const uint32_t sb = s2u(sm);
    const int tid = threadIdx.x;
    const int wid = tid >> 5, lane = tid & 31;
    const int wm = wid & 1;
    const int wn = wid >> 1;
    const int bm = blockIdx.y, bn = blockIdx.x;
    const int am0 = bm * 128, bn0 = bn * 128;

    float acc[4][4][4];
#pragma unroll
    for (int i = 0; i < 4; i++)
#pragma unroll
        for (int j = 0; j < 4; j++)
#pragma unroll
            for (int r = 0; r < 4; r++) acc[i][j][r] = 0.f;

    stage_load(Ahi, Alo, Bhi, Blo, am0, bn0, 0, sb, tid);
    CP_COMMIT();

    const int NC = GK / 64;
    for (int c = 0; c < NC; c++) {
        if (c + 1 < NC) {
            stage_load(Ahi, Alo, Bhi, Blo, am0, bn0, (c + 1) * 64,
                       sb + ((c + 1) & 1) * STAGE_B, tid);
            CP_COMMIT();
            CP_WAIT1();
        } else {
            CP_WAIT0();
        }
        __syncthreads();

        const uint32_t base = sb + (c & 1) * STAGE_B;
        const int ra = lane & 15, ca = lane >> 4;
        const int rb = lane & 7,  cb = (lane >> 3) & 1;
#pragma unroll
        for (int ks = 0; ks < 4; ks++) {
            uint32_t ah[4][4], al[4][4];
#pragma unroll
            for (int i = 0; i < 4; i++) {
                int row = wm * 64 + i * 16 + ra;
                int ch = (ks * 2 + ca) ^ (row & 7);
                uint32_t ad = base + row * 128 + ch * 16;
                ldsm_x4(ah[i], ad);
                ldsm_x4(al[i], ad + BUF_B);
            }
            uint32_t bh[4][2], bl[4][2];
#pragma unroll
            for (int j = 0; j < 4; j++) {
                int row = wn * 32 + j * 8 + rb;
                int ch = (ks * 2 + cb) ^ (row & 7);
                uint32_t bd = base + 2 * BUF_B + row * 128 + ch * 16;
                ldsm_x2(bh[j], bd);
                ldsm_x2(bl[j], bd + BUF_B);
            }
#pragma unroll
            for (int i = 0; i < 4; i++)
#pragma unroll
                for (int j = 0; j < 4; j++) {
                    mma16816(acc[i][j], ah[i], bh[j]);
                    mma16816(acc[i][j], ah[i], bl[j]);
                    mma16816(acc[i][j], al[i], bh[j]);
                }
        }
        __syncthreads();
    }

    const int r0 = lane >> 2, c0 = (lane & 3) * 2;
#pragma unroll
    for (int i = 0; i < 4; i++) {
#pragma unroll
        for (int j = 0; j < 4; j++) {
            const int grow = am0 + wm * 64 + i * 16 + r0;
            const int gcol = bn0 + wn * 32 + j * 8 + c0;
            float2 v0 = {acc[i][j][0], acc[i][j][1]};
            float2 v1 = {acc[i][j][2], acc[i][j][3]};
            *(float2*)(C + (size_t)grow * N + gcol)       = v0;
            *(float2*)(C + (size_t)(grow + 8) * N + gcol) = v1;
        }
    }
}

// ---------------------------------------------------------------------------
// Tensor-core causal flash attention, bf16 hi/lo split, 128q x 64k tiles.
// grid (L/128, H, B), 256 threads (8 warps x 16 query rows).
// smem: Qhi/Qlo 32KB + 2 stages x (Khi,Klo,Vhi,Vlo = 32KB) = 96KB
// ---------------------------------------------------------------------------
#define AT_Q    0u
#define AT_STG0 32768u
#define AT_STGB 32768u
#define SMEM_ATT 98304u

__device__ __forceinline__ void att_load_kv(const __nv_bfloat16* __restrict__ Khi,
                                            const __nv_bfloat16* __restrict__ Klo,
                                            const __nv_bfloat16* __restrict__ Vthi,
                                            const __nv_bfloat16* __restrict__ Vtlo,
                                            int b, int h, int kb,
                                            uint32_t stg, int tid) {
    const size_t kgb = (size_t)(b * SEQL + kb * 64) * DMODEL + h * DHEAD;
    const size_t vgb = (size_t)((b * NHEAD + h) * DHEAD) * SEQL + kb * 64;
#pragma unroll
    for (int t = 0; t < 2; t++) {
        int u = tid + t * 256;
        int row = u >> 3, c = u & 7;
        uint32_t soff = row * 128 + ((c ^ (row & 7)) * 16);
        cpa16(stg + soff,          Khi  + kgb + (size_t)row * DMODEL + c * 8);
        cpa16(stg + 8192 + soff,   Klo  + kgb + (size_t)row * DMODEL + c * 8);
        cpa16(stg + 16384 + soff,  Vthi + vgb + (size_t)row * SEQL + c * 8);
        cpa16(stg + 24576 + soff,  Vtlo + vgb + (size_t)row * SEQL + c * 8);
    }
}

__global__ __launch_bounds__(256) void attn_tc(const __nv_bfloat16* __restrict__ Qhi,
                                               const __nv_bfloat16* __restrict__ Qlo,
                                               const __nv_bfloat16* __restrict__ Khi,
                                               const __nv_bfloat16* __restrict__ Klo,
                                               const __nv_bfloat16* __restrict__ Vthi,
                                               const __nv_bfloat16* __restrict__ Vtlo,
                                               float* __restrict__ OUT) {
    extern __shared__ char sm[];
    const uint32_t sb = s2u(sm);
    const int tid = threadIdx.x;
    const int wid = tid >> 5, lane = tid & 31;
    const int qb = blockIdx.x, h = blockIdx.y, b = blockIdx.z;

    // Q tiles hi/lo (128 rows x 64 bf16)
    {
        const size_t qgb = (size_t)(b * SEQL + qb * 128) * DMODEL + h * DHEAD;
#pragma unroll
        for (int t = 0; t < 4; t++) {
            int u = tid + t * 256;
            int row = u >> 3, c = u & 7;
            uint32_t soff = row * 128 + ((c ^ (row & 7)) * 16);
            cpa16(sb + AT_Q + soff,         Qhi + qgb + (size_t)row * DMODEL + c * 8);
            cpa16(sb + AT_Q + 16384 + soff, Qlo + qgb + (size_t)row * DMODEL + c * 8);
        }
    }
    CP_COMMIT();

    float o[8][4];
#pragma unroll
    for (int nt = 0; nt < 8; nt++)
#pragma unroll
        for (int r = 0; r < 4; r++) o[nt][r] = 0.f;
    float m[2] = {-1e30f, -1e30f};
    float l[2] = {0.f, 0.f};

    const int qw = qb * 128 + wid * 16;      // warp's first global query row
    const int r0 = lane >> 2, c0 = (lane & 3) * 2;
    const int ra = lane & 15, ca = lane >> 4;
    const int rb = lane & 7,  cb = (lane >> 3) & 1;
    const int last = 2 * qb + 1;

    att_load_kv(Khi, Klo, Vthi, Vtlo, b, h, 0, sb + AT_STG0, tid);
    CP_COMMIT();

    for (int kb = 0; kb <= last; kb++) {
        if (kb < last) {
            att_load_kv(Khi, Klo, Vthi, Vtlo, b, h, kb + 1,
                        sb + AT_STG0 + ((kb + 1) & 1) * AT_STGB, tid);
            CP_COMMIT();
            CP_WAIT1();
        } else {
            CP_WAIT0();
        }
        __syncthreads();

        if (kb * 64 <= qw + 15) {   // tile not fully masked for this warp
            const uint32_t stg = sb + AT_STG0 + (kb & 1) * AT_STGB;

            // ---- S = Q @ K^T (split, 3 passes) ----
            float s[8][4];
#pragma unroll
            for (int nt = 0; nt < 8; nt++)
#pragma unroll
                for (int r = 0; r < 4; r++) s[nt][r] = 0.f;
#pragma unroll
            for (int ks = 0; ks < 4; ks++) {
                uint32_t ah[4], al[4];
                int arow = wid * 16 + ra;
                int ach = (ks * 2 + ca) ^ (arow & 7);
                uint32_t ad = sb + AT_Q + arow * 128 + ach * 16;
                ldsm_x4(ah, ad);
                ldsm_x4(al, ad + 16384);
#pragma unroll
                for (int nt = 0; nt < 8; nt++) {
                    int brow = nt * 8 + rb;
                    int bch = (ks * 2 + cb) ^ (brow & 7);
                    uint32_t bd = stg + brow * 128 + bch * 16;
                    uint32_t bh[2], bl[2];
                    ldsm_x2(bh, bd);
                    ldsm_x2(bl, bd + 8192);
                    mma16816(s[nt], ah, bh);
                    mma16816(s[nt], ah, bl);
                    mma16816(s[nt], al, bh);
                }
            }

            // ---- causal mask ----
            if (kb * 64 + 63 > qw) {
#pragma unroll
                for (int nt = 0; nt < 8; nt++) {
#pragma unroll
                    for (int v = 0; v < 4; v++) {
                        int kg = kb * 64 + nt * 8 + c0 + (v & 1);
                        int qg = qw + r0 + ((v >> 1) << 3);
                        if (kg > qg) s[nt][v] = -1e30f;
                    }
                }
            }

            // ---- online softmax (per row-half, row in 4-lane quad) ----
#pragma unroll
            for (int hf = 0; hf < 2; hf++) {
                float mx = -1e30f;
#pragma unroll
                for (int nt = 0; nt < 8; nt++)
                    mx = fmaxf(mx, fmaxf(s[nt][hf * 2], s[nt][hf * 2 + 1]));
                mx = fmaxf(mx, __shfl_xor_sync(0xffffffffu, mx, 1));
                mx = fmaxf(mx, __shfl_xor_sync(0xffffffffu, mx, 2));
                const float mn = fmaxf(m[hf], mx);
                const float sc = __expf(m[hf] - mn);
                float rs = 0.f;
#pragma unroll
                for (int nt = 0; nt < 8; nt++) {
                    float e0 = __expf(s[nt][hf * 2] - mn);
                    float e1 = __expf(s[nt][hf * 2 + 1] - mn);
                    s[nt][hf * 2] = e0;
                    s[nt][hf * 2 + 1] = e1;
                    rs += e0 + e1;
                }
                rs += __shfl_xor_sync(0xffffffffu, rs, 1);
                rs += __shfl_xor_sync(0xffffffffu, rs, 2);
                l[hf] = l[hf] * sc + rs;
                m[hf] = mn;
#pragma unroll
                for (int nt = 0; nt < 8; nt++) {
                    o[nt][hf * 2] *= sc;
                    o[nt][hf * 2 + 1] *= sc;
                }
            }

            // ---- O += P @ V (split, 3 passes) ----
#pragma unroll
            for (int ks = 0; ks < 4; ks++) {
                uint32_t phi[4], plo[4];
#pragma unroll
                for (int t2 = 0; t2 < 2; t2++) {
                    const float* sv = s[ks * 2 + t2];
                    float h0 = __bfloat162float(__float2bfloat16(sv[0]));
                    float h1 = __bfloat162float(__float2bfloat16(sv[1]));
                    float h2 = __bfloat162float(__float2bfloat16(sv[2]));
                    float h3 = __bfloat162float(__float2bfloat16(sv[3]));
                    phi[t2 * 2 + 0] = packbf(h0, h1);
                    phi[t2 * 2 + 1] = packbf(h2, h3);
                    plo[t2 * 2 + 0] = packbf(sv[0] - h0, sv[1] - h1);
                    plo[t2 * 2 + 1] = packbf(sv[2] - h2, sv[3] - h3);
                }
#pragma unroll
                for (int nt = 0; nt < 8; nt++) {
                    int brow = nt * 8 + rb;
                    int bch = (ks * 2 + cb) ^ (brow & 7);
                    uint32_t bd = stg + 16384 + brow * 128 + bch * 16;
                    uint32_t vh[2], vl[2];
                    ldsm_x2(vh, bd);
                    ldsm_x2(vl, bd + 8192);
                    mma16816(o[nt], phi, vh);
                    mma16816(o[nt], phi, vl);
                    mma16816(o[nt], plo, vh);
                }
            }
        }
        __syncthreads();
    }

    // ---- epilogue: O / l * 0.125 ----
    const float inv0 = 0.125f / l[0];
    const float inv1 = 0.125f / l[1];
    const size_t row0 = (size_t)(b * SEQL + qw + r0);
#pragma unroll
    for (int nt = 0; nt < 8; nt++) {
        const int col = h * DHEAD + nt * 8 + c0;
        float2 v0 = {o[nt][0] * inv0, o[nt][1] * inv0};
        float2 v1 = {o[nt][2] * inv1, o[nt][3] * inv1};
        *(float2*)(OUT + row0 * DMODEL + col)       = v0;
        *(float2*)(OUT + (row0 + 8) * DMODEL + col) = v1;
    }
}

// ---------------------------------------------------------------------------
// Launch
// ---------------------------------------------------------------------------
extern "C" void kernel_launch(void* const* d_in, const int* in_sizes, int n_in,
                              void* d_out, int out_size) {
    const float* q  = (const float*)d_in[0];
    const float* k  = (const float*)d_in[1];
    const float* v  = (const float*)d_in[2];
    const float* Wq = (const float*)d_in[4];
    const float* Wk = (const float*)d_in[5];
    const float* Wv = (const float*)d_in[6];
    const float* Wo = (const float*)d_in[7];
    float* out = (float*)d_out;

    void *pf32, *pih, *pil, *pwh, *pwl, *pqh, *pql, *pkh, *pkl, *pvh, *pvl;
    cudaGetSymbolAddress(&pf32, g_f32);
    cudaGetSymbolAddress(&pih, g_inhi);
    cudaGetSymbolAddress(&pil, g_inlo);
    cudaGetSymbolAddress(&pwh, g_wthi);
    cudaGetSymbolAddress(&pwl, g_wtlo);
    cudaGetSymbolAddress(&pqh, g_qhi);
    cudaGetSymbolAddress(&pql, g_qlo);
    cudaGetSymbolAddress(&pkh, g_khi);
    cudaGetSymbolAddress(&pkl, g_klo);
    cudaGetSymbolAddress(&pvh, g_vthi);
    cudaGetSymbolAddress(&pvl, g_vtlo);
    float* qh  = (float*)pf32;
    float* kh  = qh + (size_t)BLROWS * DMODEL;
    float* vh  = kh + (size_t)BLROWS * DMODEL;
    float* att = vh + (size_t)BLROWS * DMODEL;
    __nv_bfloat16* inhi = (__nv_bfloat16*)pih;
    __nv_bfloat16* inlo = (__nv_bfloat16*)pil;
    __nv_bfloat16* wthi = (__nv_bfloat16*)pwh;
    __nv_bfloat16* wtlo = (__nv_bfloat16*)pwl;

    cudaFuncSetAttribute(gemm_mma, cudaFuncAttributeMaxDynamicSharedMemorySize, SMEM_GEMM);
    cudaFuncSetAttribute(attn_tc, cudaFuncAttributeMaxDynamicSharedMemorySize, SMEM_ATT);

    const int n4 = (BLROWS * DMODEL) / 4;
    const dim3 cg((n4 + 255) / 256);
    const dim3 tg(DMODEL / 32, DMODEL / 32), tb(32, 8);
    const dim3 gg(DMODEL / 128, BLROWS / 128);

    const float* ins[3] = {q, k, v};
    const float* ws[3]  = {Wq, Wk, Wv};
    float* outs[3]      = {qh, kh, vh};
    for (int i = 0; i < 3; i++) {
        split_bf16<<<cg, 256>>>(ins[i], inhi, inlo, n4);
        splitT_bf16<<<tg, tb>>>(ws[i], wthi, wtlo);
        gemm_mma<<<gg, 256, SMEM_GEMM>>>(inhi, inlo, wthi, wtlo, outs[i], DMODEL);
    }

    // attention input conversions
    split_bf16<<<cg, 256>>>(qh, (__nv_bfloat16*)pqh, (__nv_bfloat16*)pql, n4);
    split_bf16<<<cg, 256>>>(kh, (__nv_bfloat16*)pkh, (__nv_bfloat16*)pkl, n4);
    vsplitT<<<dim3(SEQL / 32, DHEAD / 32, BATCH * NHEAD), tb>>>(
        vh, (__nv_bfloat16*)pvh, (__nv_bfloat16*)pvl);

    attn_tc<<<dim3(SEQL / 128, NHEAD, BATCH), 256, SMEM_ATT>>>(
        (const __nv_bfloat16*)pqh, (const __nv_bfloat16*)pql,
        (const __nv_bfloat16*)pkh, (const __nv_bfloat16*)pkl,
        (const __nv_bfloat16*)pvh, (const __nv_bfloat16*)pvl, att);

    split_bf16<<<cg, 256>>>(att, inhi, inlo, n4);
    splitT_bf16<<<tg, tb>>>(Wo, wthi, wtlo);
    gemm_mma<<<gg, 256, SMEM_GEMM>>>(inhi, inlo, wthi, wtlo, out, DMODEL);
}

// round 6
// speedup vs baseline: 3.4743x; 1.0174x over previous
#include <cuda_runtime.h>
#include <cuda_bf16.h>
#include <cstdint>

// Problem constants
#define BATCH 2
#define SEQL  2048
#define DMODEL 1024
#define NHEAD 16
#define DHEAD 64
#define BLROWS (BATCH * SEQL)   // 4096
#define GK 1024

// ---------------------------------------------------------------------------
// Scratch
// ---------------------------------------------------------------------------
__device__ float g_vh[(size_t)BLROWS * DMODEL];                         // V proj fp32
__device__ __nv_bfloat16 g_in3hi[(size_t)3 * BLROWS * DMODEL];          // q,k,v split
__device__ __nv_bfloat16 g_in3lo[(size_t)3 * BLROWS * DMODEL];
__device__ __nv_bfloat16 g_w4hi[(size_t)4 * DMODEL * DMODEL];           // Wq,Wk,Wv,Wo^T split
__device__ __nv_bfloat16 g_w4lo[(size_t)4 * DMODEL * DMODEL];
__device__ __nv_bfloat16 g_qhi[(size_t)BLROWS * DMODEL];
__device__ __nv_bfloat16 g_qlo[(size_t)BLROWS * DMODEL];
__device__ __nv_bfloat16 g_khi[(size_t)BLROWS * DMODEL];
__device__ __nv_bfloat16 g_klo[(size_t)BLROWS * DMODEL];
__device__ __nv_bfloat16 g_vthi[(size_t)BLROWS * DMODEL];               // [b,h,d,key]
__device__ __nv_bfloat16 g_vtlo[(size_t)BLROWS * DMODEL];
__device__ __nv_bfloat16 g_atthi[(size_t)BLROWS * DMODEL];
__device__ __nv_bfloat16 g_attlo[(size_t)BLROWS * DMODEL];

// ---------------------------------------------------------------------------
// PTX helpers (sm_80-level, portable to compute_103 PTX target)
// ---------------------------------------------------------------------------
__device__ __forceinline__ uint32_t s2u(const void* p) {
    uint32_t a;
    asm("{ .reg .u64 t; cvta.to.shared.u64 t, %1; cvt.u32.u64 %0, t; }"
        : "=r"(a) : "l"(p));
    return a;
}
__device__ __forceinline__ void ldsm_x4(uint32_t* r, uint32_t addr) {
    asm volatile("ldmatrix.sync.aligned.m8n8.x4.shared.b16 {%0,%1,%2,%3}, [%4];"
                 : "=r"(r[0]), "=r"(r[1]), "=r"(r[2]), "=r"(r[3]) : "r"(addr));
}
__device__ __forceinline__ void ldsm_x2(uint32_t* r, uint32_t addr) {
    asm volatile("ldmatrix.sync.aligned.m8n8.x2.shared.b16 {%0,%1}, [%2];"
                 : "=r"(r[0]), "=r"(r[1]) : "r"(addr));
}
__device__ __forceinline__ void mma16816(float* d, const uint32_t* a, const uint32_t* b) {
    asm volatile("mma.sync.aligned.m16n8k16.row.col.f32.bf16.bf16.f32 "
                 "{%0,%1,%2,%3}, {%4,%5,%6,%7}, {%8,%9}, {%0,%1,%2,%3};"
                 : "+f"(d[0]), "+f"(d[1]), "+f"(d[2]), "+f"(d[3])
                 : "r"(a[0]), "r"(a[1]), "r"(a[2]), "r"(a[3]), "r"(b[0]), "r"(b[1]));
}
__device__ __forceinline__ void cpa16(uint32_t saddr, const void* g) {
    asm volatile("cp.async.cg.shared.global [%0], [%1], 16;" :: "r"(saddr), "l"(g));
}
#define CP_COMMIT() asm volatile("cp.async.commit_group;" ::: "memory")
#define CP_WAIT1()  asm volatile("cp.async.wait_group 1;" ::: "memory")
#define CP_WAIT0()  asm volatile("cp.async.wait_group 0;" ::: "memory")

__device__ __forceinline__ uint32_t packbf(float lo, float hi) {
    uint32_t d;
    asm("cvt.rn.bf16x2.f32 %0, %1, %2;" : "=r"(d) : "f"(hi), "f"(lo));
    return d;
}

// ---------------------------------------------------------------------------
// Merged conversion kernels
// ---------------------------------------------------------------------------
// q,k,v fp32 -> in3 hi/lo.  grid (n4/256, 1, 3)
__global__ __launch_bounds__(256) void split3(const float* __restrict__ q,
                                              const float* __restrict__ k,
                                              const float* __restrict__ v,
                                              __nv_bfloat16* __restrict__ hi,
                                              __nv_bfloat16* __restrict__ lo,
                                              int n4) {
    int i = blockIdx.x * blockDim.x + threadIdx.x;
    if (i >= n4) return;
    const int z = blockIdx.z;
    const float* in = (z == 0) ? q : (z == 1) ? k : v;
    const size_t off = (size_t)z * BLROWS * DMODEL / 2;   // in bf16x2 units
    float4 val = ((const float4*)in)[i];
    __nv_bfloat16 h0 = __float2bfloat16(val.x);
    __nv_bfloat16 h1 = __float2bfloat16(val.y);
    __nv_bfloat16 h2 = __float2bfloat16(val.z);
    __nv_bfloat16 h3 = __float2bfloat16(val.w);
    __nv_bfloat16 l0 = __float2bfloat16(val.x - __bfloat162float(h0));
    __nv_bfloat16 l1 = __float2bfloat16(val.y - __bfloat162float(h1));
    __nv_bfloat16 l2 = __float2bfloat16(val.z - __bfloat162float(h2));
    __nv_bfloat16 l3 = __float2bfloat16(val.w - __bfloat162float(h3));
    ((__nv_bfloat162*)hi)[off + 2 * i]     = __nv_bfloat162(h0, h1);
    ((__nv_bfloat162*)hi)[off + 2 * i + 1] = __nv_bfloat162(h2, h3);
    ((__nv_bfloat162*)lo)[off + 2 * i]     = __nv_bfloat162(l0, l1);
    ((__nv_bfloat162*)lo)[off + 2 * i + 1] = __nv_bfloat162(l2, l3);
}

// W [K][N] fp32 -> Wt hi/lo [N][K] bf16, all four weights.  grid (32, 32, 4)
__global__ __launch_bounds__(256) void splitT4(const float* __restrict__ w0,
                                               const float* __restrict__ w1,
                                               const float* __restrict__ w2,
                                               const float* __restrict__ w3,
                                               __nv_bfloat16* __restrict__ th,
                                               __nv_bfloat16* __restrict__ tl) {
    __shared__ float t[32][33];
    const int tx = threadIdx.x, ty = threadIdx.y;
    const int n0 = blockIdx.x * 32, k0 = blockIdx.y * 32;
    const int z = blockIdx.z;
    const float* W = (z == 0) ? w0 : (z == 1) ? w1 : (z == 2) ? w2 : w3;
    const size_t zoff = (size_t)z * DMODEL * DMODEL;
#pragma unroll
    for (int i = 0; i < 32; i += 8)
        t[ty + i][tx] = W[(size_t)(k0 + ty + i) * DMODEL + n0 + tx];
    __syncthreads();
#pragma unroll
    for (int i = 0; i < 32; i += 8) {
        float x = t[tx][ty + i];
        __nv_bfloat16 h = __float2bfloat16(x);
        __nv_bfloat16 l = __float2bfloat16(x - __bfloat162float(h));
        size_t o = zoff + (size_t)(n0 + ty + i) * DMODEL + k0 + tx;
        th[o] = h;
        tl[o] = l;
    }
}

// vh fp32 [b][tok][dmodel] -> Vt hi/lo [b,h,d][key]
__global__ __launch_bounds__(256) void vsplitT(const float* __restrict__ V,
                                               __nv_bfloat16* __restrict__ th,
                                               __nv_bfloat16* __restrict__ tl) {
    __shared__ float t[32][33];
    const int tx = threadIdx.x, ty = threadIdx.y;
    const int t0 = blockIdx.x * 32, d0 = blockIdx.y * 32;
    const int bh = blockIdx.z;
    const int b = bh >> 4, h = bh & 15;
#pragma unroll
    for (int i = 0; i < 32; i += 8)
        t[ty + i][tx] = V[(size_t)(b * SEQL + t0 + ty + i) * DMODEL + h * DHEAD + d0 + tx];
    __syncthreads();
#pragma unroll
    for (int i = 0; i < 32; i += 8) {
        float x = t[tx][ty + i];
        __nv_bfloat16 hh = __float2bfloat16(x);
        __nv_bfloat16 ll = __float2bfloat16(x - __bfloat162float(hh));
        size_t o = (size_t)(bh * DHEAD + d0 + ty + i) * SEQL + t0 + tx;
        th[o] = hh;
        tl[o] = ll;
    }
}

// ---------------------------------------------------------------------------
// bf16 split-MMA GEMM; epilogue writes fp32 (BFOUT=false) or bf16 hi/lo split.
// ---------------------------------------------------------------------------
#define BUF_B   16384u
#define STAGE_B 65536u
#define SMEM_GEMM (2u * STAGE_B)

__device__ __forceinline__ void stage_load(const __nv_bfloat16* __restrict__ Ahi,
                                           const __nv_bfloat16* __restrict__ Alo,
                                           const __nv_bfloat16* __restrict__ Bhi,
                                           const __nv_bfloat16* __restrict__ Blo,
                                           int am0, int bn0, int k0,
                                           uint32_t sbase, int tid) {
#pragma unroll
    for (int b = 0; b < 4; b++) {
        const __nv_bfloat16* g = (b == 0) ? Ahi : (b == 1) ? Alo : (b == 2) ? Bhi : Blo;
        const int r0 = (b < 2) ? am0 : bn0;
        const uint32_t sbuf = sbase + b * BUF_B;
#pragma unroll
        for (int t = 0; t < 4; t++) {
            int u = tid + t * 256;
            int row = u >> 3, c = u & 7;
            int sw = c ^ (row & 7);
            cpa16(sbuf + row * 128 + sw * 16,
                  g + (size_t)(r0 + row) * GK + k0 + c * 8);
        }
    }
}

template <bool BFOUT>
__global__ __launch_bounds__(256) void gemm_mma(const __nv_bfloat16* __restrict__ Ahi,
                                                const __nv_bfloat16* __restrict__ Alo,
                                                const __nv_bfloat16* __restrict__ Bhi,
                                                const __nv_bfloat16* __restrict__ Blo,
                                                float* __restrict__ C,
                                                __nv_bfloat16* __restrict__ Chi,
                                                __nv_bfloat16* __restrict__ Clo,
                                                int N) {
    extern __shared__ char sm[];
    const uint32_t sb = s2u(sm);
    const int tid = threadIdx.x;
    const int wid = tid >> 5, lane = tid & 31;
    const int wm = wid & 1;
    const int wn = wid >> 1;
    const int bm = blockIdx.y, bn = blockIdx.x;
    const int am0 = bm * 128, bn0 = bn * 128;

    float acc[4][4][4];
#pragma unroll
    for (int i = 0; i < 4; i++)
#pragma unroll
        for (int j = 0; j < 4; j++)
#pragma unroll
            for (int r = 0; r < 4; r++) acc[i][j][r] = 0.f;

    stage_load(Ahi, Alo, Bhi, Blo, am0, bn0, 0, sb, tid);
    CP_COMMIT();

    const int NC = GK / 64;
    for (int c = 0; c < NC; c++) {
        if (c + 1 < NC) {
            stage_load(Ahi, Alo, Bhi, Blo, am0, bn0, (c + 1) * 64,
                       sb + ((c + 1) & 1) * STAGE_B, tid);
            CP_COMMIT();
            CP_WAIT1();
        } else {
            CP_WAIT0();
        }
        __syncthreads();

        const uint32_t base = sb + (c & 1) * STAGE_B;
        const int ra = lane & 15, ca = lane >> 4;
        const int rb = lane & 7,  cb = (lane >> 3) & 1;
#pragma unroll
        for (int ks = 0; ks < 4; ks++) {
            uint32_t ah[4][4], al[4][4];
#pragma unroll
            for (int i = 0; i < 4; i++) {
                int row = wm * 64 + i * 16 + ra;
                int ch = (ks * 2 + ca) ^ (row & 7);
                uint32_t ad = base + row * 128 + ch * 16;
                ldsm_x4(ah[i], ad);
                ldsm_x4(al[i], ad + BUF_B);
            }
            uint32_t bh[4][2], bl[4][2];
#pragma unroll
            for (int j = 0; j < 4; j++) {
                int row = wn * 32 + j * 8 + rb;
                int ch = (ks * 2 + cb) ^ (row & 7);
                uint32_t bd = base + 2 * BUF_B + row * 128 + ch * 16;
                ldsm_x2(bh[j], bd);
                ldsm_x2(bl[j], bd + BUF_B);
            }
#pragma unroll
            for (int i = 0; i < 4; i++)
#pragma unroll
                for (int j = 0; j < 4; j++) {
                    mma16816(acc[i][j], ah[i], bh[j]);
                    mma16816(acc[i][j], ah[i], bl[j]);
                    mma16816(acc[i][j], al[i], bh[j]);
                }
        }
        __syncthreads();
    }

    const int r0 = lane >> 2, c0 = (lane & 3) * 2;
#pragma unroll
    for (int i = 0; i < 4; i++) {
#pragma unroll
        for (int j = 0; j < 4; j++) {
            const int grow = am0 + wm * 64 + i * 16 + r0;
            const int gcol = bn0 + wn * 32 + j * 8 + c0;
            if (!BFOUT) {
                float2 v0 = {acc[i][j][0], acc[i][j][1]};
                float2 v1 = {acc[i][j][2], acc[i][j][3]};
                *(float2*)(C + (size_t)grow * N + gcol)       = v0;
                *(float2*)(C + (size_t)(grow + 8) * N + gcol) = v1;
            } else {
#pragma unroll
                for (int half = 0; half < 2; half++) {
                    float a0 = acc[i][j][half * 2], a1 = acc[i][j][half * 2 + 1];
                    float h0 = __bfloat162float(__float2bfloat16(a0));
                    float h1 = __bfloat162float(__float2bfloat16(a1));
                    size_t o = (size_t)(grow + half * 8) * N + gcol;
                    *(uint32_t*)(Chi + o) = packbf(h0, h1);
                    *(uint32_t*)(Clo + o) = packbf(a0 - h0, a1 - h1);
                }
            }
        }
    }
}

// ---------------------------------------------------------------------------
// Tensor-core causal flash attention, bf16 hi/lo split, 128q x 64k tiles.
// Writes att directly as bf16 hi/lo (input for the Wo GEMM).
// ---------------------------------------------------------------------------
#define AT_Q    0u
#define AT_STG0 32768u
#define AT_STGB 32768u
#define SMEM_ATT 98304u

__device__ __forceinline__ void att_load_kv(const __nv_bfloat16* __restrict__ Khi,
                                            const __nv_bfloat16* __restrict__ Klo,
                                            const __nv_bfloat16* __restrict__ Vthi,
                                            const __nv_bfloat16* __restrict__ Vtlo,
                                            int b, int h, int kb,
                                            uint32_t stg, int tid) {
    const size_t kgb = (size_t)(b * SEQL + kb * 64) * DMODEL + h * DHEAD;
    const size_t vgb = (size_t)((b * NHEAD + h) * DHEAD) * SEQL + kb * 64;
#pragma unroll
    for (int t = 0; t < 2; t++) {
        int u = tid + t * 256;
        int row = u >> 3, c = u & 7;
        uint32_t soff = row * 128 + ((c ^ (row & 7)) * 16);
        cpa16(stg + soff,          Khi  + kgb + (size_t)row * DMODEL + c * 8);
        cpa16(stg + 8192 + soff,   Klo  + kgb + (size_t)row * DMODEL + c * 8);
        cpa16(stg + 16384 + soff,  Vthi + vgb + (size_t)row * SEQL + c * 8);
        cpa16(stg + 24576 + soff,  Vtlo + vgb + (size_t)row * SEQL + c * 8);
    }
}

__global__ __launch_bounds__(256) void attn_tc(const __nv_bfloat16* __restrict__ Qhi,
                                               const __nv_bfloat16* __restrict__ Qlo,
                                               const __nv_bfloat16* __restrict__ Khi,
                                               const __nv_bfloat16* __restrict__ Klo,
                                               const __nv_bfloat16* __restrict__ Vthi,
                                               const __nv_bfloat16* __restrict__ Vtlo,
                                               __nv_bfloat16* __restrict__ Ohi,
                                               __nv_bfloat16* __restrict__ Olo) {
    extern __shared__ char sm[];
    const uint32_t sb = s2u(sm);
    const int tid = threadIdx.x;
    const int wid = tid >> 5, lane = tid & 31;
    const int qb = blockIdx.x, h = blockIdx.y, b = blockIdx.z;

    {
        const size_t qgb = (size_t)(b * SEQL + qb * 128) * DMODEL + h * DHEAD;
#pragma unroll
        for (int t = 0; t < 4; t++) {
            int u = tid + t * 256;
            int row = u >> 3, c = u & 7;
            uint32_t soff = row * 128 + ((c ^ (row & 7)) * 16);
            cpa16(sb + AT_Q + soff,         Qhi + qgb + (size_t)row * DMODEL + c * 8);
            cpa16(sb + AT_Q + 16384 + soff, Qlo + qgb + (size_t)row * DMODEL + c * 8);
        }
    }
    CP_COMMIT();

    float o[8][4];
#pragma unroll
    for (int nt = 0; nt < 8; nt++)
#pragma unroll
        for (int r = 0; r < 4; r++) o[nt][r] = 0.f;
    float m[2] = {-1e30f, -1e30f};
    float l[2] = {0.f, 0.f};

    const int qw = qb * 128 + wid * 16;
    const int r0 = lane >> 2, c0 = (lane & 3) * 2;
    const int ra = lane & 15, ca = lane >> 4;
    const int rb = lane & 7,  cb = (lane >> 3) & 1;
    const int last = 2 * qb + 1;

    att_load_kv(Khi, Klo, Vthi, Vtlo, b, h, 0, sb + AT_STG0, tid);
    CP_COMMIT();

    for (int kb = 0; kb <= last; kb++) {
        if (kb < last) {
            att_load_kv(Khi, Klo, Vthi, Vtlo, b, h, kb + 1,
                        sb + AT_STG0 + ((kb + 1) & 1) * AT_STGB, tid);
            CP_COMMIT();
            CP_WAIT1();
        } else {
            CP_WAIT0();
        }
        __syncthreads();

        if (kb * 64 <= qw + 15) {
            const uint32_t stg = sb + AT_STG0 + (kb & 1) * AT_STGB;

            float s[8][4];
#pragma unroll
            for (int nt = 0; nt < 8; nt++)
#pragma unroll
                for (int r = 0; r < 4; r++) s[nt][r] = 0.f;
#pragma unroll
            for (int ks = 0; ks < 4; ks++) {
                uint32_t ah[4], al[4];
                int arow = wid * 16 + ra;
                int ach = (ks * 2 + ca) ^ (arow & 7);
                uint32_t ad = sb + AT_Q + arow * 128 + ach * 16;
                ldsm_x4(ah, ad);
                ldsm_x4(al, ad + 16384);
#pragma unroll
                for (int nt = 0; nt < 8; nt++) {
                    int brow = nt * 8 + rb;
                    int bch = (ks * 2 + cb) ^ (brow & 7);
                    uint32_t bd = stg + brow * 128 + bch * 16;
                    uint32_t bh[2], bl[2];
                    ldsm_x2(bh, bd);
                    ldsm_x2(bl, bd + 8192);
                    mma16816(s[nt], ah, bh);
                    mma16816(s[nt], ah, bl);
                    mma16816(s[nt], al, bh);
                }
            }

            if (kb * 64 + 63 > qw) {
#pragma unroll
                for (int nt = 0; nt < 8; nt++) {
#pragma unroll
                    for (int v = 0; v < 4; v++) {
                        int kg = kb * 64 + nt * 8 + c0 + (v & 1);
                        int qg = qw + r0 + ((v >> 1) << 3);
                        if (kg > qg) s[nt][v] = -1e30f;
                    }
                }
            }

#pragma unroll
            for (int hf = 0; hf < 2; hf++) {
                float mx = -1e30f;
#pragma unroll
                for (int nt = 0; nt < 8; nt++)
                    mx = fmaxf(mx, fmaxf(s[nt][hf * 2], s[nt][hf * 2 + 1]));
                mx = fmaxf(mx, __shfl_xor_sync(0xffffffffu, mx, 1));
                mx = fmaxf(mx, __shfl_xor_sync(0xffffffffu, mx, 2));
                const float mn = fmaxf(m[hf], mx);
                const float sc = __expf(m[hf] - mn);
                float rs = 0.f;
#pragma unroll
                for (int nt = 0; nt < 8; nt++) {
                    float e0 = __expf(s[nt][hf * 2] - mn);
                    float e1 = __expf(s[nt][hf * 2 + 1] - mn);
                    s[nt][hf * 2] = e0;
                    s[nt][hf * 2 + 1] = e1;
                    rs += e0 + e1;
                }
                rs += __shfl_xor_sync(0xffffffffu, rs, 1);
                rs += __shfl_xor_sync(0xffffffffu, rs, 2);
                l[hf] = l[hf] * sc + rs;
                m[hf] = mn;
#pragma unroll
                for (int nt = 0; nt < 8; nt++) {
                    o[nt][hf * 2] *= sc;
                    o[nt][hf * 2 + 1] *= sc;
                }
            }

#pragma unroll
            for (int ks = 0; ks < 4; ks++) {
                uint32_t phi[4], plo[4];
#pragma unroll
                for (int t2 = 0; t2 < 2; t2++) {
                    const float* sv = s[ks * 2 + t2];
                    float h0 = __bfloat162float(__float2bfloat16(sv[0]));
                    float h1 = __bfloat162float(__float2bfloat16(sv[1]));
                    float h2 = __bfloat162float(__float2bfloat16(sv[2]));
                    float h3 = __bfloat162float(__float2bfloat16(sv[3]));
                    phi[t2 * 2 + 0] = packbf(h0, h1);
                    phi[t2 * 2 + 1] = packbf(h2, h3);
                    plo[t2 * 2 + 0] = packbf(sv[0] - h0, sv[1] - h1);
                    plo[t2 * 2 + 1] = packbf(sv[2] - h2, sv[3] - h3);
                }
#pragma unroll
                for (int nt = 0; nt < 8; nt++) {
                    int brow = nt * 8 + rb;
                    int bch = (ks * 2 + cb) ^ (brow & 7);
                    uint32_t bd = stg + 16384 + brow * 128 + bch * 16;
                    uint32_t vh[2], vl[2];
                    ldsm_x2(vh, bd);
                    ldsm_x2(vl, bd + 8192);
                    mma16816(o[nt], phi, vh);
                    mma16816(o[nt], phi, vl);
                    mma16816(o[nt], plo, vh);
                }
            }
        }
        __syncthreads();
    }

    // epilogue: att = O / l * 0.125, written as bf16 hi/lo split
    const float inv0 = 0.125f / l[0];
    const float inv1 = 0.125f / l[1];
    const size_t row0 = (size_t)(b * SEQL + qw + r0);
#pragma unroll
    for (int nt = 0; nt < 8; nt++) {
        const int col = h * DHEAD + nt * 8 + c0;
        float a0 = o[nt][0] * inv0, a1 = o[nt][1] * inv0;
        float a2 = o[nt][2] * inv1, a3 = o[nt][3] * inv1;
        float h0 = __bfloat162float(__float2bfloat16(a0));
        float h1 = __bfloat162float(__float2bfloat16(a1));
        float h2 = __bfloat162float(__float2bfloat16(a2));
        float h3 = __bfloat162float(__float2bfloat16(a3));
        size_t o0 = row0 * DMODEL + col;
        size_t o1 = (row0 + 8) * DMODEL + col;
        *(uint32_t*)(Ohi + o0) = packbf(h0, h1);
        *(uint32_t*)(Olo + o0) = packbf(a0 - h0, a1 - h1);
        *(uint32_t*)(Ohi + o1) = packbf(h2, h3);
        *(uint32_t*)(Olo + o1) = packbf(a2 - h2, a3 - h3);
    }
}

// ---------------------------------------------------------------------------
// Launch
// ---------------------------------------------------------------------------
extern "C" void kernel_launch(void* const* d_in, const int* in_sizes, int n_in,
                              void* d_out, int out_size) {
    const float* q  = (const float*)d_in[0];
    const float* k  = (const float*)d_in[1];
    const float* v  = (const float*)d_in[2];
    const float* Wq = (const float*)d_in[4];
    const float* Wk = (const float*)d_in[5];
    const float* Wv = (const float*)d_in[6];
    const float* Wo = (const float*)d_in[7];
    float* out = (float*)d_out;

    void *pvh, *pi3h, *pi3l, *pw4h, *pw4l, *pqh, *pql, *pkh, *pkl, *pvth, *pvtl, *pah, *pal;
    cudaGetSymbolAddress(&pvh, g_vh);
    cudaGetSymbolAddress(&pi3h, g_in3hi);
    cudaGetSymbolAddress(&pi3l, g_in3lo);
    cudaGetSymbolAddress(&pw4h, g_w4hi);
    cudaGetSymbolAddress(&pw4l, g_w4lo);
    cudaGetSymbolAddress(&pqh, g_qhi);
    cudaGetSymbolAddress(&pql, g_qlo);
    cudaGetSymbolAddress(&pkh, g_khi);
    cudaGetSymbolAddress(&pkl, g_klo);
    cudaGetSymbolAddress(&pvth, g_vthi);
    cudaGetSymbolAddress(&pvtl, g_vtlo);
    cudaGetSymbolAddress(&pah, g_atthi);
    cudaGetSymbolAddress(&pal, g_attlo);

    __nv_bfloat16* i3h = (__nv_bfloat16*)pi3h;
    __nv_bfloat16* i3l = (__nv_bfloat16*)pi3l;
    __nv_bfloat16* w4h = (__nv_bfloat16*)pw4h;
    __nv_bfloat16* w4l = (__nv_bfloat16*)pw4l;
    const size_t IS = (size_t)BLROWS * DMODEL;
    const size_t WS = (size_t)DMODEL * DMODEL;

    cudaFuncSetAttribute(gemm_mma<false>, cudaFuncAttributeMaxDynamicSharedMemorySize, SMEM_GEMM);
    cudaFuncSetAttribute(gemm_mma<true>,  cudaFuncAttributeMaxDynamicSharedMemorySize, SMEM_GEMM);
    cudaFuncSetAttribute(attn_tc, cudaFuncAttributeMaxDynamicSharedMemorySize, SMEM_ATT);

    const int n4 = (BLROWS * DMODEL) / 4;
    const dim3 tb(32, 8);
    const dim3 gg(DMODEL / 128, BLROWS / 128);

    split3<<<dim3((n4 + 255) / 256, 1, 3), 256>>>(q, k, v, i3h, i3l, n4);
    splitT4<<<dim3(32, 32, 4), tb>>>(Wq, Wk, Wv, Wo, w4h, w4l);

    // Q, K projections -> bf16 hi/lo directly
    gemm_mma<true><<<gg, 256, SMEM_GEMM>>>(i3h, i3l, w4h, w4l,
                                           nullptr, (__nv_bfloat16*)pqh, (__nv_bfloat16*)pql, DMODEL);
    gemm_mma<true><<<gg, 256, SMEM_GEMM>>>(i3h + IS, i3l + IS, w4h + WS, w4l + WS,
                                           nullptr, (__nv_bfloat16*)pkh, (__nv_bfloat16*)pkl, DMODEL);
    // V projection -> fp32 (for transposed split)
    gemm_mma<false><<<gg, 256, SMEM_GEMM>>>(i3h + 2 * IS, i3l + 2 * IS, w4h + 2 * WS, w4l + 2 * WS,
                                            (float*)pvh, nullptr, nullptr, DMODEL);
    vsplitT<<<dim3(SEQL / 32, DHEAD / 32, BATCH * NHEAD), tb>>>(
        (const float*)pvh, (__nv_bfloat16*)pvth, (__nv_bfloat16*)pvtl);

    attn_tc<<<dim3(SEQL / 128, NHEAD, BATCH), 256, SMEM_ATT>>>(
        (const __nv_bfloat16*)pqh, (const __nv_bfloat16*)pql,
        (const __nv_bfloat16*)pkh, (const __nv_bfloat16*)pkl,
        (const __nv_bfloat16*)pvth, (const __nv_bfloat16*)pvtl,
        (__nv_bfloat16*)pah, (__nv_bfloat16*)pal);

    gemm_mma<false><<<gg, 256, SMEM_GEMM>>>((const __nv_bfloat16*)pah, (const __nv_bfloat16*)pal,
                                            w4h + 3 * WS, w4l + 3 * WS, out, nullptr, nullptr, DMODEL);
}

// round 7
// speedup vs baseline: 3.9270x; 1.1303x over previous
#include <cuda_runtime.h>
#include <cuda_bf16.h>
#include <cstdint>

// Problem constants
#define BATCH 2
#define SEQL  2048
#define DMODEL 1024
#define NHEAD 16
#define DHEAD 64
#define BLROWS (BATCH * SEQL)   // 4096
#define GK 1024

// ---------------------------------------------------------------------------
// Scratch
// ---------------------------------------------------------------------------
__device__ float g_vh[(size_t)BLROWS * DMODEL];                         // V proj fp32
__device__ __nv_bfloat16 g_in3hi[(size_t)3 * BLROWS * DMODEL];          // q,k,v split
__device__ __nv_bfloat16 g_in3lo[(size_t)3 * BLROWS * DMODEL];
__device__ __nv_bfloat16 g_w4hi[(size_t)4 * DMODEL * DMODEL];           // Wq,Wk,Wv,Wo^T split
__device__ __nv_bfloat16 g_w4lo[(size_t)4 * DMODEL * DMODEL];
__device__ __nv_bfloat16 g_qhi[(size_t)BLROWS * DMODEL];
__device__ __nv_bfloat16 g_qlo[(size_t)BLROWS * DMODEL];
__device__ __nv_bfloat16 g_khi[(size_t)BLROWS * DMODEL];
__device__ __nv_bfloat16 g_klo[(size_t)BLROWS * DMODEL];
__device__ __nv_bfloat16 g_vthi[(size_t)BLROWS * DMODEL];               // [b,h,d,key]
__device__ __nv_bfloat16 g_vtlo[(size_t)BLROWS * DMODEL];
__device__ __nv_bfloat16 g_atthi[(size_t)BLROWS * DMODEL];
__device__ __nv_bfloat16 g_attlo[(size_t)BLROWS * DMODEL];

// ---------------------------------------------------------------------------
// PTX helpers
// ---------------------------------------------------------------------------
__device__ __forceinline__ uint32_t s2u(const void* p) {
    uint32_t a;
    asm("{ .reg .u64 t; cvta.to.shared.u64 t, %1; cvt.u32.u64 %0, t; }"
        : "=r"(a) : "l"(p));
    return a;
}
__device__ __forceinline__ void ldsm_x4(uint32_t* r, uint32_t addr) {
    asm volatile("ldmatrix.sync.aligned.m8n8.x4.shared.b16 {%0,%1,%2,%3}, [%4];"
                 : "=r"(r[0]), "=r"(r[1]), "=r"(r[2]), "=r"(r[3]) : "r"(addr));
}
__device__ __forceinline__ void ldsm_x2(uint32_t* r, uint32_t addr) {
    asm volatile("ldmatrix.sync.aligned.m8n8.x2.shared.b16 {%0,%1}, [%2];"
                 : "=r"(r[0]), "=r"(r[1]) : "r"(addr));
}
__device__ __forceinline__ void mma16816(float* d, const uint32_t* a, const uint32_t* b) {
    asm volatile("mma.sync.aligned.m16n8k16.row.col.f32.bf16.bf16.f32 "
                 "{%0,%1,%2,%3}, {%4,%5,%6,%7}, {%8,%9}, {%0,%1,%2,%3};"
                 : "+f"(d[0]), "+f"(d[1]), "+f"(d[2]), "+f"(d[3])
                 : "r"(a[0]), "r"(a[1]), "r"(a[2]), "r"(a[3]), "r"(b[0]), "r"(b[1]));
}
__device__ __forceinline__ void cpa16(uint32_t saddr, const void* g) {
    asm volatile("cp.async.cg.shared.global [%0], [%1], 16;" :: "r"(saddr), "l"(g));
}
#define CP_COMMIT() asm volatile("cp.async.commit_group;" ::: "memory")
#define CP_WAIT1()  asm volatile("cp.async.wait_group 1;" ::: "memory")
#define CP_WAIT0()  asm volatile("cp.async.wait_group 0;" ::: "memory")

__device__ __forceinline__ uint32_t packbf(float lo, float hi) {
    uint32_t d;
    asm("cvt.rn.bf16x2.f32 %0, %1, %2;" : "=r"(d) : "f"(hi), "f"(lo));
    return d;
}

// ---------------------------------------------------------------------------
// Conversion kernels
// ---------------------------------------------------------------------------
__global__ __launch_bounds__(256) void split3(const float* __restrict__ q,
                                              const float* __restrict__ k,
                                              const float* __restrict__ v,
                                              __nv_bfloat16* __restrict__ hi,
                                              __nv_bfloat16* __restrict__ lo,
                                              int n4) {
    int i = blockIdx.x * blockDim.x + threadIdx.x;
    if (i >= n4) return;
    const int z = blockIdx.z;
    const float* in = (z == 0) ? q : (z == 1) ? k : v;
    const size_t off = (size_t)z * BLROWS * DMODEL / 2;
    float4 val = ((const float4*)in)[i];
    __nv_bfloat16 h0 = __float2bfloat16(val.x);
    __nv_bfloat16 h1 = __float2bfloat16(val.y);
    __nv_bfloat16 h2 = __float2bfloat16(val.z);
    __nv_bfloat16 h3 = __float2bfloat16(val.w);
    __nv_bfloat16 l0 = __float2bfloat16(val.x - __bfloat162float(h0));
    __nv_bfloat16 l1 = __float2bfloat16(val.y - __bfloat162float(h1));
    __nv_bfloat16 l2 = __float2bfloat16(val.z - __bfloat162float(h2));
    __nv_bfloat16 l3 = __float2bfloat16(val.w - __bfloat162float(h3));
    ((__nv_bfloat162*)hi)[off + 2 * i]     = __nv_bfloat162(h0, h1);
    ((__nv_bfloat162*)hi)[off + 2 * i + 1] = __nv_bfloat162(h2, h3);
    ((__nv_bfloat162*)lo)[off + 2 * i]     = __nv_bfloat162(l0, l1);
    ((__nv_bfloat162*)lo)[off + 2 * i + 1] = __nv_bfloat162(l2, l3);
}

__global__ __launch_bounds__(256) void splitT4(const float* __restrict__ w0,
                                               const float* __restrict__ w1,
                                               const float* __restrict__ w2,
                                               const float* __restrict__ w3,
                                               __nv_bfloat16* __restrict__ th,
                                               __nv_bfloat16* __restrict__ tl) {
    __shared__ float t[32][33];
    const int tx = threadIdx.x, ty = threadIdx.y;
    const int n0 = blockIdx.x * 32, k0 = blockIdx.y * 32;
    const int z = blockIdx.z;
    const float* W = (z == 0) ? w0 : (z == 1) ? w1 : (z == 2) ? w2 : w3;
    const size_t zoff = (size_t)z * DMODEL * DMODEL;
#pragma unroll
    for (int i = 0; i < 32; i += 8)
        t[ty + i][tx] = W[(size_t)(k0 + ty + i) * DMODEL + n0 + tx];
    __syncthreads();
#pragma unroll
    for (int i = 0; i < 32; i += 8) {
        float x = t[tx][ty + i];
        __nv_bfloat16 h = __float2bfloat16(x);
        __nv_bfloat16 l = __float2bfloat16(x - __bfloat162float(h));
        size_t o = zoff + (size_t)(n0 + ty + i) * DMODEL + k0 + tx;
        th[o] = h;
        tl[o] = l;
    }
}

__global__ __launch_bounds__(256) void vsplitT(const float* __restrict__ V,
                                               __nv_bfloat16* __restrict__ th,
                                               __nv_bfloat16* __restrict__ tl) {
    __shared__ float t[32][33];
    const int tx = threadIdx.x, ty = threadIdx.y;
    const int t0 = blockIdx.x * 32, d0 = blockIdx.y * 32;
    const int bh = blockIdx.z;
    const int b = bh >> 4, h = bh & 15;
#pragma unroll
    for (int i = 0; i < 32; i += 8)
        t[ty + i][tx] = V[(size_t)(b * SEQL + t0 + ty + i) * DMODEL + h * DHEAD + d0 + tx];
    __syncthreads();
#pragma unroll
    for (int i = 0; i < 32; i += 8) {
        float x = t[tx][ty + i];
        __nv_bfloat16 hh = __float2bfloat16(x);
        __nv_bfloat16 ll = __float2bfloat16(x - __bfloat162float(hh));
        size_t o = (size_t)(bh * DHEAD + d0 + ty + i) * SEQL + t0 + tx;
        th[o] = hh;
        tl[o] = ll;
    }
}

// ---------------------------------------------------------------------------
// bf16 split-MMA GEMM, 3-stage pipeline, K-chunk 32, 2 CTAs/SM.
// 64B rows, swizzle ch = c ^ ((row>>1)&3).
// ---------------------------------------------------------------------------
#define GBUF   8192u                 // one 128x32 bf16 tile
#define GSTG   32768u                // 4 tiles per stage
#define SMEM_GEMM (3u * GSTG)        // 98304

__device__ __forceinline__ void stage_load32(const __nv_bfloat16* __restrict__ Ahi,
                                             const __nv_bfloat16* __restrict__ Alo,
                                             const __nv_bfloat16* __restrict__ Bhi,
                                             const __nv_bfloat16* __restrict__ Blo,
                                             int am0, int bn0, int k0,
                                             uint32_t sbase, int tid) {
#pragma unroll
    for (int b = 0; b < 4; b++) {
        const __nv_bfloat16* g = (b == 0) ? Ahi : (b == 1) ? Alo : (b == 2) ? Bhi : Blo;
        const int r0 = (b < 2) ? am0 : bn0;
        const uint32_t sbuf = sbase + b * GBUF;
#pragma unroll
        for (int t = 0; t < 2; t++) {
            int u = tid + t * 256;
            int row = u >> 2, c = u & 3;
            int sw = c ^ ((row >> 1) & 3);
            cpa16(sbuf + row * 64 + sw * 16,
                  g + (size_t)(r0 + row) * GK + k0 + c * 8);
        }
    }
}

template <bool BFOUT>
__global__ __launch_bounds__(256, 2) void gemm_mma(const __nv_bfloat16* __restrict__ Ahi,
                                                   const __nv_bfloat16* __restrict__ Alo,
                                                   const __nv_bfloat16* __restrict__ Bhi,
                                                   const __nv_bfloat16* __restrict__ Blo,
                                                   float* __restrict__ C,
                                                   __nv_bfloat16* __restrict__ Chi,
                                                   __nv_bfloat16* __restrict__ Clo,
                                                   int N) {
    extern __shared__ char sm[];
    const uint32_t sb = s2u(sm);
    const int tid = threadIdx.x;
    const int wid = tid >> 5, lane = tid & 31;
    const int wm = wid & 1;
    const int wn = wid >> 1;
    const int bm = blockIdx.y, bn = blockIdx.x;
    const int am0 = bm * 128, bn0 = bn * 128;

    float acc[4][4][4];
#pragma unroll
    for (int i = 0; i < 4; i++)
#pragma unroll
        for (int j = 0; j < 4; j++)
#pragma unroll
            for (int r = 0; r < 4; r++) acc[i][j][r] = 0.f;

    const int NC = GK / 32;          // 32 chunks
    stage_load32(Ahi, Alo, Bhi, Blo, am0, bn0, 0, sb, tid);
    CP_COMMIT();
    stage_load32(Ahi, Alo, Bhi, Blo, am0, bn0, 32, sb + GSTG, tid);
    CP_COMMIT();

    const int ra = lane & 15, ca = lane >> 4;
    const int rb = lane & 7,  cb = (lane >> 3) & 1;
    int stg = 0;
    for (int c = 0; c < NC; c++) {
        if (c < NC - 1) CP_WAIT1(); else CP_WAIT0();
        __syncthreads();

        const uint32_t base = sb + stg * GSTG;
#pragma unroll
        for (int ks = 0; ks < 2; ks++) {
            uint32_t ah[4][4], al[4][4];
#pragma unroll
            for (int i = 0; i < 4; i++) {
                int row = wm * 64 + i * 16 + ra;
                int ch = (ks * 2 + ca) ^ ((row >> 1) & 3);
                uint32_t ad = base + row * 64 + ch * 16;
                ldsm_x4(ah[i], ad);
                ldsm_x4(al[i], ad + GBUF);
            }
            uint32_t bh[4][2], bl[4][2];
#pragma unroll
            for (int j = 0; j < 4; j++) {
                int row = wn * 32 + j * 8 + rb;
                int ch = (ks * 2 + cb) ^ ((row >> 1) & 3);
                uint32_t bd = base + 2 * GBUF + row * 64 + ch * 16;
                ldsm_x2(bh[j], bd);
                ldsm_x2(bl[j], bd + GBUF);
            }
#pragma unroll
            for (int i = 0; i < 4; i++)
#pragma unroll
                for (int j = 0; j < 4; j++) {
                    mma16816(acc[i][j], ah[i], bh[j]);
                    mma16816(acc[i][j], ah[i], bl[j]);
                    mma16816(acc[i][j], al[i], bh[j]);
                }
        }

        if (c + 2 < NC) {
            stage_load32(Ahi, Alo, Bhi, Blo, am0, bn0, (c + 2) * 32,
                         sb + ((stg + 2) % 3) * GSTG, tid);
            CP_COMMIT();
        }
        stg = (stg + 1) % 3;
    }

    const int r0 = lane >> 2, c0 = (lane & 3) * 2;
#pragma unroll
    for (int i = 0; i < 4; i++) {
#pragma unroll
        for (int j = 0; j < 4; j++) {
            const int grow = am0 + wm * 64 + i * 16 + r0;
            const int gcol = bn0 + wn * 32 + j * 8 + c0;
            if (!BFOUT) {
                float2 v0 = {acc[i][j][0], acc[i][j][1]};
                float2 v1 = {acc[i][j][2], acc[i][j][3]};
                *(float2*)(C + (size_t)grow * N + gcol)       = v0;
                *(float2*)(C + (size_t)(grow + 8) * N + gcol) = v1;
            } else {
#pragma unroll
                for (int half = 0; half < 2; half++) {
                    float a0 = acc[i][j][half * 2], a1 = acc[i][j][half * 2 + 1];
                    float h0 = __bfloat162float(__float2bfloat16(a0));
                    float h1 = __bfloat162float(__float2bfloat16(a1));
                    size_t o = (size_t)(grow + half * 8) * N + gcol;
                    *(uint32_t*)(Chi + o) = packbf(h0, h1);
                    *(uint32_t*)(Clo + o) = packbf(a0 - h0, a1 - h1);
                }
            }
        }
    }
}

// ---------------------------------------------------------------------------
// Tensor-core causal flash attention, bf16 hi/lo split, 128q x 64k tiles.
// grid (bh=32, qb=16) with qb reversed (heavy tiles first). 2 CTAs/SM.
// ---------------------------------------------------------------------------
#define AT_Q    0u
#define AT_STG0 32768u
#define AT_STGB 32768u
#define SMEM_ATT 98304u

__device__ __forceinline__ void att_load_kv(const __nv_bfloat16* __restrict__ Khi,
                                            const __nv_bfloat16* __restrict__ Klo,
                                            const __nv_bfloat16* __restrict__ Vthi,
                                            const __nv_bfloat16* __restrict__ Vtlo,
                                            int b, int h, int kb,
                                            uint32_t stg, int tid) {
    const size_t kgb = (size_t)(b * SEQL + kb * 64) * DMODEL + h * DHEAD;
    const size_t vgb = (size_t)((b * NHEAD + h) * DHEAD) * SEQL + kb * 64;
#pragma unroll
    for (int t = 0; t < 2; t++) {
        int u = tid + t * 256;
        int row = u >> 3, c = u & 7;
        uint32_t soff = row * 128 + ((c ^ (row & 7)) * 16);
        cpa16(stg + soff,          Khi  + kgb + (size_t)row * DMODEL + c * 8);
        cpa16(stg + 8192 + soff,   Klo  + kgb + (size_t)row * DMODEL + c * 8);
        cpa16(stg + 16384 + soff,  Vthi + vgb + (size_t)row * SEQL + c * 8);
        cpa16(stg + 24576 + soff,  Vtlo + vgb + (size_t)row * SEQL + c * 8);
    }
}

__global__ __launch_bounds__(256, 2) void attn_tc(const __nv_bfloat16* __restrict__ Qhi,
                                                  const __nv_bfloat16* __restrict__ Qlo,
                                                  const __nv_bfloat16* __restrict__ Khi,
                                                  const __nv_bfloat16* __restrict__ Klo,
                                                  const __nv_bfloat16* __restrict__ Vthi,
                                                  const __nv_bfloat16* __restrict__ Vtlo,
                                                  __nv_bfloat16* __restrict__ Ohi,
                                                  __nv_bfloat16* __restrict__ Olo) {
    extern __shared__ char sm[];
    const uint32_t sb = s2u(sm);
    const int tid = threadIdx.x;
    const int wid = tid >> 5, lane = tid & 31;
    const int qb = (int)gridDim.y - 1 - (int)blockIdx.y;   // heavy tiles first
    const int h = blockIdx.x & 15, b = blockIdx.x >> 4;

    {
        const size_t qgb = (size_t)(b * SEQL + qb * 128) * DMODEL + h * DHEAD;
#pragma unroll
        for (int t = 0; t < 4; t++) {
            int u = tid + t * 256;
            int row = u >> 3, c = u & 7;
            uint32_t soff = row * 128 + ((c ^ (row & 7)) * 16);
            cpa16(sb + AT_Q + soff,         Qhi + qgb + (size_t)row * DMODEL + c * 8);
            cpa16(sb + AT_Q + 16384 + soff, Qlo + qgb + (size_t)row * DMODEL + c * 8);
        }
    }
    CP_COMMIT();

    float o[8][4];
#pragma unroll
    for (int nt = 0; nt < 8; nt++)
#pragma unroll
        for (int r = 0; r < 4; r++) o[nt][r] = 0.f;
    float m[2] = {-1e30f, -1e30f};
    float l[2] = {0.f, 0.f};

    const int qw = qb * 128 + wid * 16;
    const int r0 = lane >> 2, c0 = (lane & 3) * 2;
    const int ra = lane & 15, ca = lane >> 4;
    const int rb = lane & 7,  cb = (lane >> 3) & 1;
    const int last = 2 * qb + 1;

    att_load_kv(Khi, Klo, Vthi, Vtlo, b, h, 0, sb + AT_STG0, tid);
    CP_COMMIT();

    for (int kb = 0; kb <= last; kb++) {
        if (kb < last) {
            att_load_kv(Khi, Klo, Vthi, Vtlo, b, h, kb + 1,
                        sb + AT_STG0 + ((kb + 1) & 1) * AT_STGB, tid);
            CP_COMMIT();
            CP_WAIT1();
        } else {
            CP_WAIT0();
        }
        __syncthreads();

        if (kb * 64 <= qw + 15) {
            const uint32_t stg = sb + AT_STG0 + (kb & 1) * AT_STGB;

            float s[8][4];
#pragma unroll
            for (int nt = 0; nt < 8; nt++)
#pragma unroll
                for (int r = 0; r < 4; r++) s[nt][r] = 0.f;
#pragma unroll
            for (int ks = 0; ks < 4; ks++) {
                uint32_t ah[4], al[4];
                int arow = wid * 16 + ra;
                int ach = (ks * 2 + ca) ^ (arow & 7);
                uint32_t ad = sb + AT_Q + arow * 128 + ach * 16;
                ldsm_x4(ah, ad);
                ldsm_x4(al, ad + 16384);
#pragma unroll
                for (int nt = 0; nt < 8; nt++) {
                    int brow = nt * 8 + rb;
                    int bch = (ks * 2 + cb) ^ (brow & 7);
                    uint32_t bd = stg + brow * 128 + bch * 16;
                    uint32_t bh[2], bl[2];
                    ldsm_x2(bh, bd);
                    ldsm_x2(bl, bd + 8192);
                    mma16816(s[nt], ah, bh);
                    mma16816(s[nt], ah, bl);
                    mma16816(s[nt], al, bh);
                }
            }

            if (kb * 64 + 63 > qw) {
#pragma unroll
                for (int nt = 0; nt < 8; nt++) {
#pragma unroll
                    for (int v = 0; v < 4; v++) {
                        int kg = kb * 64 + nt * 8 + c0 + (v & 1);
                        int qg = qw + r0 + ((v >> 1) << 3);
                        if (kg > qg) s[nt][v] = -1e30f;
                    }
                }
            }

#pragma unroll
            for (int hf = 0; hf < 2; hf++) {
                float mx = -1e30f;
#pragma unroll
                for (int nt = 0; nt < 8; nt++)
                    mx = fmaxf(mx, fmaxf(s[nt][hf * 2], s[nt][hf * 2 + 1]));
                mx = fmaxf(mx, __shfl_xor_sync(0xffffffffu, mx, 1));
                mx = fmaxf(mx, __shfl_xor_sync(0xffffffffu, mx, 2));
                const float mn = fmaxf(m[hf], mx);
                const float sc = __expf(m[hf] - mn);
                float rs = 0.f;
#pragma unroll
                for (int nt = 0; nt < 8; nt++) {
                    float e0 = __expf(s[nt][hf * 2] - mn);
                    float e1 = __expf(s[nt][hf * 2 + 1] - mn);
                    s[nt][hf * 2] = e0;
                    s[nt][hf * 2 + 1] = e1;
                    rs += e0 + e1;
                }
                rs += __shfl_xor_sync(0xffffffffu, rs, 1);
                rs += __shfl_xor_sync(0xffffffffu, rs, 2);
                l[hf] = l[hf] * sc + rs;
                m[hf] = mn;
#pragma unroll
                for (int nt = 0; nt < 8; nt++) {
                    o[nt][hf * 2] *= sc;
                    o[nt][hf * 2 + 1] *= sc;
                }
            }

#pragma unroll
            for (int ks = 0; ks < 4; ks++) {
                uint32_t phi[4], plo[4];
#pragma unroll
                for (int t2 = 0; t2 < 2; t2++) {
                    const float* sv = s[ks * 2 + t2];
                    float h0 = __bfloat162float(__float2bfloat16(sv[0]));
                    float h1 = __bfloat162float(__float2bfloat16(sv[1]));
                    float h2 = __bfloat162float(__float2bfloat16(sv[2]));
                    float h3 = __bfloat162float(__float2bfloat16(sv[3]));
                    phi[t2 * 2 + 0] = packbf(h0, h1);
                    phi[t2 * 2 + 1] = packbf(h2, h3);
                    plo[t2 * 2 + 0] = packbf(sv[0] - h0, sv[1] - h1);
                    plo[t2 * 2 + 1] = packbf(sv[2] - h2, sv[3] - h3);
                }
#pragma unroll
                for (int nt = 0; nt < 8; nt++) {
                    int brow = nt * 8 + rb;
                    int bch = (ks * 2 + cb) ^ (brow & 7);
                    uint32_t bd = stg + 16384 + brow * 128 + bch * 16;
                    uint32_t vh[2], vl[2];
                    ldsm_x2(vh, bd);
                    ldsm_x2(vl, bd + 8192);
                    mma16816(o[nt], phi, vh);
                    mma16816(o[nt], phi, vl);
                    mma16816(o[nt], plo, vh);
                }
            }
        }
        __syncthreads();
    }

    const float inv0 = 0.125f / l[0];
    const float inv1 = 0.125f / l[1];
    const size_t row0 = (size_t)(b * SEQL + qw + r0);
#pragma unroll
    for (int nt = 0; nt < 8; nt++) {
        const int col = h * DHEAD + nt * 8 + c0;
        float a0 = o[nt][0] * inv0, a1 = o[nt][1] * inv0;
        float a2 = o[nt][2] * inv1, a3 = o[nt][3] * inv1;
        float h0 = __bfloat162float(__float2bfloat16(a0));
        float h1 = __bfloat162float(__float2bfloat16(a1));
        float h2 = __bfloat162float(__float2bfloat16(a2));
        float h3 = __bfloat162float(__float2bfloat16(a3));
        size_t o0 = row0 * DMODEL + col;
        size_t o1 = (row0 + 8) * DMODEL + col;
        *(uint32_t*)(Ohi + o0) = packbf(h0, h1);
        *(uint32_t*)(Olo + o0) = packbf(a0 - h0, a1 - h1);
        *(uint32_t*)(Ohi + o1) = packbf(h2, h3);
        *(uint32_t*)(Olo + o1) = packbf(a2 - h2, a3 - h3);
    }
}

// ---------------------------------------------------------------------------
// Launch
// ---------------------------------------------------------------------------
extern "C" void kernel_launch(void* const* d_in, const int* in_sizes, int n_in,
                              void* d_out, int out_size) {
    const float* q  = (const float*)d_in[0];
    const float* k  = (const float*)d_in[1];
    const float* v  = (const float*)d_in[2];
    const float* Wq = (const float*)d_in[4];
    const float* Wk = (const float*)d_in[5];
    const float* Wv = (const float*)d_in[6];
    const float* Wo = (const float*)d_in[7];
    float* out = (float*)d_out;

    void *pvh, *pi3h, *pi3l, *pw4h, *pw4l, *pqh, *pql, *pkh, *pkl, *pvth, *pvtl, *pah, *pal;
    cudaGetSymbolAddress(&pvh, g_vh);
    cudaGetSymbolAddress(&pi3h, g_in3hi);
    cudaGetSymbolAddress(&pi3l, g_in3lo);
    cudaGetSymbolAddress(&pw4h, g_w4hi);
    cudaGetSymbolAddress(&pw4l, g_w4lo);
    cudaGetSymbolAddress(&pqh, g_qhi);
    cudaGetSymbolAddress(&pql, g_qlo);
    cudaGetSymbolAddress(&pkh, g_khi);
    cudaGetSymbolAddress(&pkl, g_klo);
    cudaGetSymbolAddress(&pvth, g_vthi);
    cudaGetSymbolAddress(&pvtl, g_vtlo);
    cudaGetSymbolAddress(&pah, g_atthi);
    cudaGetSymbolAddress(&pal, g_attlo);

    __nv_bfloat16* i3h = (__nv_bfloat16*)pi3h;
    __nv_bfloat16* i3l = (__nv_bfloat16*)pi3l;
    __nv_bfloat16* w4h = (__nv_bfloat16*)pw4h;
    __nv_bfloat16* w4l = (__nv_bfloat16*)pw4l;
    const size_t IS = (size_t)BLROWS * DMODEL;
    const size_t WS = (size_t)DMODEL * DMODEL;

    cudaFuncSetAttribute(gemm_mma<false>, cudaFuncAttributeMaxDynamicSharedMemorySize, SMEM_GEMM);
    cudaFuncSetAttribute(gemm_mma<true>,  cudaFuncAttributeMaxDynamicSharedMemorySize, SMEM_GEMM);
    cudaFuncSetAttribute(attn_tc, cudaFuncAttributeMaxDynamicSharedMemorySize, SMEM_ATT);

    const int n4 = (BLROWS * DMODEL) / 4;
    const dim3 tb(32, 8);
    const dim3 gg(DMODEL / 128, BLROWS / 128);

    split3<<<dim3((n4 + 255) / 256, 1, 3), 256>>>(q, k, v, i3h, i3l, n4);
    splitT4<<<dim3(32, 32, 4), tb>>>(Wq, Wk, Wv, Wo, w4h, w4l);

    gemm_mma<true><<<gg, 256, SMEM_GEMM>>>(i3h, i3l, w4h, w4l,
                                           nullptr, (__nv_bfloat16*)pqh, (__nv_bfloat16*)pql, DMODEL);
    gemm_mma<true><<<gg, 256, SMEM_GEMM>>>(i3h + IS, i3l + IS, w4h + WS, w4l + WS,
                                           nullptr, (__nv_bfloat16*)pkh, (__nv_bfloat16*)pkl, DMODEL);
    gemm_mma<false><<<gg, 256, SMEM_GEMM>>>(i3h + 2 * IS, i3l + 2 * IS, w4h + 2 * WS, w4l + 2 * WS,
                                            (float*)pvh, nullptr, nullptr, DMODEL);
    vsplitT<<<dim3(SEQL / 32, DHEAD / 32, BATCH * NHEAD), tb>>>(
        (const float*)pvh, (__nv_bfloat16*)pvth, (__nv_bfloat16*)pvtl);

    attn_tc<<<dim3(NHEAD * BATCH, SEQL / 128, 1), 256, SMEM_ATT>>>(
        (const __nv_bfloat16*)pqh, (const __nv_bfloat16*)pql,
        (const __nv_bfloat16*)pkh, (const __nv_bfloat16*)pkl,
        (const __nv_bfloat16*)pvth, (const __nv_bfloat16*)pvtl,
        (__nv_bfloat16*)pah, (__nv_bfloat16*)pal);

    gemm_mma<false><<<gg, 256, SMEM_GEMM>>>((const __nv_bfloat16*)pah, (const __nv_bfloat16*)pal,
                                            w4h + 3 * WS, w4l + 3 * WS, out, nullptr, nullptr, DMODEL);
}